// round 2
// baseline (speedup 1.0000x reference)
#include <cuda_runtime.h>
#include <cstdint>

// Problem constants (ModulatedDeformConv2d): B=4, C=64, H=W=96, O=64, 3x3,
// stride=1, pad=1, dil=1, groups=1, DG=1.
#define BB 4
#define CC 64
#define HH 96
#define WW 96
#define OO 64
#define KHH 3
#define KWW 3
#define KK 9            // KH*KW
#define CKK 576         // C*K
#define HOO 96
#define WOO 96
#define HW (HH*WW)

#define TP 32           // pixels per block (contiguous wo segment)
#define THREADS 256

// shared layout
#define S_BYTES   (CKK * TP * 4)            // 73728
#define IDX_BYTES (TP * KK * 16)            // 4608 (int4 per (p,k))
#define WGT_BYTES (TP * KK * 16)            // 4608 (float4 per (p,k))
#define SMEM_TOTAL (S_BYTES + IDX_BYTES + WGT_BYTES)

__device__ __forceinline__ void fma2(unsigned long long &d,
                                     unsigned long long a,
                                     unsigned long long b) {
    asm("fma.rn.f32x2 %0, %1, %2, %0;" : "+l"(d) : "l"(a), "l"(b));
}

__device__ __forceinline__ unsigned long long bcast2(float w) {
    unsigned long long r;
    asm("mov.b64 %0, {%1, %1};" : "=l"(r) : "f"(w));
    return r;
}

__device__ __forceinline__ void unpack2(unsigned long long v, float &lo, float &hi) {
    asm("mov.b64 {%0, %1}, %2;" : "=f"(lo), "=f"(hi) : "l"(v));
}

__global__ __launch_bounds__(THREADS)
void dcn_kernel(const float* __restrict__ x,
                const float* __restrict__ offset,
                const float* __restrict__ mask,
                const float* __restrict__ weight,
                const float* __restrict__ bias,
                float* __restrict__ out) {
    extern __shared__ char smem_raw[];
    float* s          = reinterpret_cast<float*>(smem_raw);               // [CKK][TP]
    int4*  sidx       = reinterpret_cast<int4*>(smem_raw + S_BYTES);      // [TP*KK]
    float4* swgt      = reinterpret_cast<float4*>(smem_raw + S_BYTES + IDX_BYTES);

    const int t   = threadIdx.x;
    const int wo0 = blockIdx.x * TP;
    const int ho  = blockIdx.y;
    const int b   = blockIdx.z;

    // ---------------- Phase 0: per-(pixel,tap) bilinear params ----------------
    {
        const float* offb  = offset + (size_t)b * (2 * KK * HOO * WOO);
        const float* maskb = mask   + (size_t)b * (KK * HOO * WOO);
        for (int i = t; i < TP * KK; i += THREADS) {
            const int p  = i / KK;
            const int k  = i - p * KK;
            const int wo = wo0 + p;
            const int ky = k / KWW;
            const int kx = k - ky * KWW;

            const float off_y = offb[((2 * k + 0) * HOO + ho) * WOO + wo];
            const float off_x = offb[((2 * k + 1) * HOO + ho) * WOO + wo];
            const float m     = maskb[(k * HOO + ho) * WOO + wo];

            const float py = (float)(ho - 1 + ky) + off_y;   // stride=1, pad=1, dil=1
            const float px = (float)(wo - 1 + kx) + off_x;

            const float y0f = floorf(py);
            const float x0f = floorf(px);
            const int y0 = (int)y0f;
            const int x0 = (int)x0f;
            const float ly = py - y0f;
            const float lx = px - x0f;
            const float hy = 1.0f - ly;
            const float hx = 1.0f - lx;

            const int y1 = y0 + 1;
            const int x1 = x0 + 1;

            const float vy0 = (y0 >= 0 && y0 < HH) ? 1.0f : 0.0f;
            const float vy1 = (y1 >= 0 && y1 < HH) ? 1.0f : 0.0f;
            const float vx0 = (x0 >= 0 && x0 < WW) ? 1.0f : 0.0f;
            const float vx1 = (x1 >= 0 && x1 < WW) ? 1.0f : 0.0f;

            const int cy0 = min(max(y0, 0), HH - 1);
            const int cy1 = min(max(y1, 0), HH - 1);
            const int cx0 = min(max(x0, 0), WW - 1);
            const int cx1 = min(max(x1, 0), WW - 1);

            int4 id;
            id.x = cy0 * WW + cx0;
            id.y = cy0 * WW + cx1;
            id.z = cy1 * WW + cx0;
            id.w = cy1 * WW + cx1;

            float4 w4;
            w4.x = hy * hx * m * vy0 * vx0;
            w4.y = hy * lx * m * vy0 * vx1;
            w4.z = ly * hx * m * vy1 * vx0;
            w4.w = ly * lx * m * vy1 * vx1;

            sidx[p * KK + k] = id;
            swgt[p * KK + k] = w4;
        }
    }
    __syncthreads();

    // ---------------- Phase 1: sampling into s[ck][p] ----------------
    {
        const float* xb0 = x + (size_t)b * CC * HW;
        // CKK*TP / THREADS = 72 iterations exactly
        #pragma unroll 4
        for (int slot = t; slot < CKK * TP; slot += THREADS) {
            const int p  = slot & (TP - 1);
            const int ck = slot >> 5;          // TP == 32
            const int c  = ck / KK;
            const int k  = ck - c * KK;
            const int4   id = sidx[p * KK + k];
            const float4 w4 = swgt[p * KK + k];
            const float* xb = xb0 + (size_t)c * HW;
            float v = w4.x * __ldg(xb + id.x)
                    + w4.y * __ldg(xb + id.y)
                    + w4.z * __ldg(xb + id.z)
                    + w4.w * __ldg(xb + id.w);
            s[ck * TP + p] = v;
        }
    }
    __syncthreads();

    // ---------------- Phase 2: 64x576 GEMM against staged samples ----------------
    {
        const int o   = t >> 2;          // 0..63
        const int pg  = t & 3;           // 0..3
        const int px0 = pg * 8;          // 8 pixels per thread

        const float* wrow = weight + (size_t)o * CKK;

        unsigned long long acc0 = 0ull, acc1 = 0ull, acc2 = 0ull, acc3 = 0ull;

        #pragma unroll 8
        for (int ck = 0; ck < CKK; ck++) {
            const float wv = __ldg(wrow + ck);
            const unsigned long long w2 = bcast2(wv);
            const ulonglong2* sp =
                reinterpret_cast<const ulonglong2*>(s + ck * TP + px0);
            const ulonglong2 q0 = sp[0];
            const ulonglong2 q1 = sp[1];
            fma2(acc0, q0.x, w2);
            fma2(acc1, q0.y, w2);
            fma2(acc2, q1.x, w2);
            fma2(acc3, q1.y, w2);
        }

        const float bv = __ldg(bias + o);
        float* ob = out + (((size_t)b * OO + o) * HOO + ho) * WOO + wo0 + px0;

        float lo, hi;
        unpack2(acc0, lo, hi);
        reinterpret_cast<float2*>(ob)[0] = make_float2(lo + bv, hi + bv);
        unpack2(acc1, lo, hi);
        reinterpret_cast<float2*>(ob)[1] = make_float2(lo + bv, hi + bv);
        unpack2(acc2, lo, hi);
        reinterpret_cast<float2*>(ob)[2] = make_float2(lo + bv, hi + bv);
        unpack2(acc3, lo, hi);
        reinterpret_cast<float2*>(ob)[3] = make_float2(lo + bv, hi + bv);
    }
}

extern "C" void kernel_launch(void* const* d_in, const int* in_sizes, int n_in,
                              void* d_out, int out_size) {
    const float* x      = (const float*)d_in[0];
    const float* offset = (const float*)d_in[1];
    const float* mask   = (const float*)d_in[2];
    const float* weight = (const float*)d_in[3];
    const float* bias   = (const float*)d_in[4];
    float* out = (float*)d_out;

    cudaFuncSetAttribute(dcn_kernel,
                         cudaFuncAttributeMaxDynamicSharedMemorySize, SMEM_TOTAL);

    dim3 grid(WOO / TP, HOO, BB);   // (3, 96, 4) = 1152 blocks
    dcn_kernel<<<grid, THREADS, SMEM_TOTAL>>>(x, offset, mask, weight, bias, out);
}

// round 3
// speedup vs baseline: 1.3134x; 1.3134x over previous
#include <cuda_runtime.h>
#include <cstdint>

// ModulatedDeformConv2d: B=4, C=64, H=W=96, O=64, 3x3, stride=1, pad=1, dil=1, DG=1.
#define BB 4
#define CC 64
#define HH 96
#define WW 96
#define OO 64
#define KWW 3
#define KK 9
#define CKK 576
#define HOO 96
#define WOO 96
#define HW (HH*WW)

#define TP 32           // pixels per block
#define THREADS 256

#define S_BYTES   (CKK * TP * 4)            // 73728
#define IDX_BYTES (TP * KK * 16)
#define WGT_BYTES (TP * KK * 16)
#define SMEM_TOTAL (S_BYTES + IDX_BYTES + WGT_BYTES)

// Transposed + duplicated weight: wT[ck][o] = {w[o][ck], w[o][ck]} (float2).
__device__ float2 g_wT[CKK * OO];

__device__ __forceinline__ void fma2(unsigned long long &d,
                                     unsigned long long a,
                                     unsigned long long b) {
    asm("fma.rn.f32x2 %0, %1, %2, %0;" : "+l"(d) : "l"(a), "l"(b));
}

__device__ __forceinline__ void unpack2(unsigned long long v, float &lo, float &hi) {
    asm("mov.b64 {%0, %1}, %2;" : "=f"(lo), "=f"(hi) : "l"(v));
}

__global__ void prep_weight_kernel(const float* __restrict__ weight) {
    int idx = blockIdx.x * blockDim.x + threadIdx.x;   // 0 .. CKK*OO-1
    if (idx >= CKK * OO) return;
    int ck = idx >> 6;           // /64
    int o  = idx & 63;
    float w = weight[o * CKK + ck];
    g_wT[idx] = make_float2(w, w);
}

__global__ __launch_bounds__(THREADS)
void dcn_kernel(const float* __restrict__ x,
                const float* __restrict__ offset,
                const float* __restrict__ mask,
                const float* __restrict__ bias,
                float* __restrict__ out) {
    extern __shared__ char smem_raw[];
    float*  s    = reinterpret_cast<float*>(smem_raw);                      // [CKK][TP]
    int4*   sidx = reinterpret_cast<int4*>(smem_raw + S_BYTES);             // [TP*KK]
    float4* swgt = reinterpret_cast<float4*>(smem_raw + S_BYTES + IDX_BYTES);

    const int t   = threadIdx.x;
    const int wo0 = blockIdx.x * TP;
    const int ho  = blockIdx.y;
    const int b   = blockIdx.z;

    // ---------------- Phase 0: per-(pixel,tap) bilinear params ----------------
    {
        const float* offb  = offset + (size_t)b * (2 * KK * HOO * WOO);
        const float* maskb = mask   + (size_t)b * (KK * HOO * WOO);
        for (int i = t; i < TP * KK; i += THREADS) {
            const int p  = i / KK;
            const int k  = i - p * KK;
            const int wo = wo0 + p;
            const int ky = k / KWW;
            const int kx = k - ky * KWW;

            const float off_y = offb[((2 * k + 0) * HOO + ho) * WOO + wo];
            const float off_x = offb[((2 * k + 1) * HOO + ho) * WOO + wo];
            const float m     = maskb[(k * HOO + ho) * WOO + wo];

            const float py = (float)(ho - 1 + ky) + off_y;
            const float px = (float)(wo - 1 + kx) + off_x;

            const float y0f = floorf(py);
            const float x0f = floorf(px);
            const int y0 = (int)y0f;
            const int x0 = (int)x0f;
            const float ly = py - y0f;
            const float lx = px - x0f;
            const float hy = 1.0f - ly;
            const float hx = 1.0f - lx;

            const int y1 = y0 + 1;
            const int x1 = x0 + 1;

            const float vy0 = (y0 >= 0 && y0 < HH) ? 1.0f : 0.0f;
            const float vy1 = (y1 >= 0 && y1 < HH) ? 1.0f : 0.0f;
            const float vx0 = (x0 >= 0 && x0 < WW) ? 1.0f : 0.0f;
            const float vx1 = (x1 >= 0 && x1 < WW) ? 1.0f : 0.0f;

            const int cy0 = min(max(y0, 0), HH - 1);
            const int cy1 = min(max(y1, 0), HH - 1);
            const int cx0 = min(max(x0, 0), WW - 1);
            const int cx1 = min(max(x1, 0), WW - 1);

            int4 id;
            id.x = cy0 * WW + cx0;
            id.y = cy0 * WW + cx1;
            id.z = cy1 * WW + cx0;
            id.w = cy1 * WW + cx1;

            float4 w4;
            w4.x = hy * hx * m * vy0 * vx0;
            w4.y = hy * lx * m * vy0 * vx1;
            w4.z = ly * hx * m * vy1 * vx0;
            w4.w = ly * lx * m * vy1 * vx1;

            sidx[p * KK + k] = id;
            swgt[p * KK + k] = w4;
        }
    }
    __syncthreads();

    // ---------------- Phase 1: bilinear sampling into s[ck][p] ----------------
    {
        const float* xb0 = x + (size_t)b * CC * HW;
        #pragma unroll 4
        for (int slot = t; slot < CKK * TP; slot += THREADS) {
            const int p  = slot & (TP - 1);
            const int ck = slot >> 5;
            const int c  = ck / KK;
            const int k  = ck - c * KK;
            const int4   id = sidx[p * KK + k];
            const float4 w4 = swgt[p * KK + k];
            const float* xb = xb0 + (size_t)c * HW;
            float v = w4.x * __ldg(xb + id.x)
                    + w4.y * __ldg(xb + id.y)
                    + w4.z * __ldg(xb + id.z)
                    + w4.w * __ldg(xb + id.w);
            s[ck * TP + p] = v;
        }
    }
    __syncthreads();

    // ---------------- Phase 2: 64x576 GEMM, 2 outputs x 4 pixels per thread ----------------
    {
        const int oq = t >> 3;           // 0..31 -> outputs 2*oq, 2*oq+1
        const int pg = t & 7;            // 0..7  -> pixels 4*pg .. 4*pg+3

        unsigned long long a00 = 0ull, a01 = 0ull, a10 = 0ull, a11 = 0ull;

        // wT row ck: 64 float2 (= 32 ulonglong2 pairs). Thread reads pair index oq.
        const char* wbase = reinterpret_cast<const char*>(g_wT) + oq * sizeof(ulonglong2);
        const char* sbase = reinterpret_cast<const char*>(s)    + pg * sizeof(ulonglong2);

        #pragma unroll 4
        for (int ck = 0; ck < CKK; ck++) {
            const ulonglong2 wv = __ldg(reinterpret_cast<const ulonglong2*>(
                                        wbase + (size_t)ck * (OO * sizeof(float2))));
            const ulonglong2 sv = *reinterpret_cast<const ulonglong2*>(
                                        sbase + (size_t)ck * (TP * sizeof(float)));
            fma2(a00, sv.x, wv.x);   // output o0, pixels 0-1
            fma2(a01, sv.y, wv.x);   // output o0, pixels 2-3
            fma2(a10, sv.x, wv.y);   // output o1, pixels 0-1
            fma2(a11, sv.y, wv.y);   // output o1, pixels 2-3
        }

        const int o0 = 2 * oq;
        const float bv0 = __ldg(bias + o0);
        const float bv1 = __ldg(bias + o0 + 1);

        float* ob0 = out + (((size_t)b * OO + o0) * HOO + ho) * WOO + wo0 + pg * 4;
        float* ob1 = ob0 + (size_t)HOO * WOO;

        float lo, hi;
        unpack2(a00, lo, hi);
        reinterpret_cast<float2*>(ob0)[0] = make_float2(lo + bv0, hi + bv0);
        unpack2(a01, lo, hi);
        reinterpret_cast<float2*>(ob0)[1] = make_float2(lo + bv0, hi + bv0);
        unpack2(a10, lo, hi);
        reinterpret_cast<float2*>(ob1)[0] = make_float2(lo + bv1, hi + bv1);
        unpack2(a11, lo, hi);
        reinterpret_cast<float2*>(ob1)[1] = make_float2(lo + bv1, hi + bv1);
    }
}

extern "C" void kernel_launch(void* const* d_in, const int* in_sizes, int n_in,
                              void* d_out, int out_size) {
    const float* x      = (const float*)d_in[0];
    const float* offset = (const float*)d_in[1];
    const float* mask   = (const float*)d_in[2];
    const float* weight = (const float*)d_in[3];
    const float* bias   = (const float*)d_in[4];
    float* out = (float*)d_out;

    prep_weight_kernel<<<(CKK * OO + 255) / 256, 256>>>(weight);

    cudaFuncSetAttribute(dcn_kernel,
                         cudaFuncAttributeMaxDynamicSharedMemorySize, SMEM_TOTAL);

    dim3 grid(WOO / TP, HOO, BB);   // (3, 96, 4)
    dcn_kernel<<<grid, THREADS, SMEM_TOTAL>>>(x, offset, mask, bias, out);
}

// round 9
// speedup vs baseline: 3.6682x; 2.7930x over previous
#include <cuda_runtime.h>
#include <cuda_bf16.h>
#include <cstdint>

// ModulatedDeformConv2d: B=4, C=64, H=W=96, O=64, 3x3, stride=1, pad=1, dil=1, DG=1.
#define BB 4
#define CC 64
#define HH 96
#define WW 96
#define OO 64
#define KK 9
#define HW (HH*WW)
#define NPX (96*96)         // 9216 output pixels per image
#define MPX 128             // pixels per block (GEMM M)
#define THREADS 256
#define CHUNKS 9            // one chunk per 3x3 tap, K=64 channels each
#define KSTEPS 4            // 64 / 16

// ---- shared memory layout ----
#define A_HI_OFF 0          // 128 rows x 128B (bf16 hi), SW128
#define A_LO_OFF 16384      // 128 rows x 128B (bf16 lo), SW128
#define PIDX_OFF 32768      // int4 [MPX*KK]   18432B  (reused as epilogue buffer)
#define PWGT_OFF (PIDX_OFF + 18432)      // float4 [MPX*KK] 18432B
#define SMEM_TOTAL (PWGT_OFF + 18432)    // 69632

#define SOUT_STRIDE 132     // epilogue: s_out[o][px], padded stride (floats)

__device__ __forceinline__ uint32_t smem_u32(const void* p) {
    uint32_t a;
    asm("{ .reg .u64 t; cvta.to.shared.u64 t, %1; cvt.u32.u64 %0, t; }" : "=r"(a) : "l"(p));
    return a;
}
__device__ __forceinline__ uint32_t sw128(uint32_t off) {
    return off ^ ((off >> 3) & 0x70);
}

__device__ __forceinline__ void ldmatrix_x4(uint32_t &r0, uint32_t &r1,
                                            uint32_t &r2, uint32_t &r3, uint32_t addr) {
    asm volatile("ldmatrix.sync.aligned.m8n8.x4.shared.b16 {%0,%1,%2,%3}, [%4];"
                 : "=r"(r0), "=r"(r1), "=r"(r2), "=r"(r3) : "r"(addr));
}

__device__ __forceinline__ void mma_bf16(float &d0, float &d1, float &d2, float &d3,
                                         uint32_t a0, uint32_t a1, uint32_t a2, uint32_t a3,
                                         uint32_t b0, uint32_t b1) {
    asm volatile("mma.sync.aligned.m16n8k16.row.col.f32.bf16.bf16.f32 "
                 "{%0,%1,%2,%3}, {%4,%5,%6,%7}, {%8,%9}, {%0,%1,%2,%3};"
                 : "+f"(d0), "+f"(d1), "+f"(d2), "+f"(d3)
                 : "r"(a0), "r"(a1), "r"(a2), "r"(a3), "r"(b0), "r"(b1));
}

// Pre-packed B fragments, exact mma.sync lane order.
// Index: ((chunk*KSTEPS + kstep)*8 + ntile)*32 + lane  ->  {bhi0, bhi1, blo0, blo1}
__device__ __align__(16) uint4 g_Bfrag[CHUNKS * KSTEPS * 8 * 32];

__global__ void prep_weight_kernel(const float* __restrict__ weight) {
    const int idx = blockIdx.x * blockDim.x + threadIdx.x;   // 0 .. 9216-1
    if (idx >= CHUNKS * KSTEPS * 8 * 32) return;
    const int lane  = idx & 31;
    const int ntile = (idx >> 5) & 7;
    const int kstep = (idx >> 8) & 3;
    const int chunk = idx >> 10;

    const int n  = ntile * 8 + (lane >> 2);          // output channel o
    const int c0 = kstep * 16 + 2 * (lane & 3);      // input channel pair base

    uint32_t h[2], l[2];
    #pragma unroll
    for (int half = 0; half < 2; half++) {           // b0 (k), b1 (k+8)
        const int ca = c0 + half * 8;
        float w0 = weight[n * (CC * KK) + ca * KK + chunk];
        float w1 = weight[n * (CC * KK) + (ca + 1) * KK + chunk];
        __nv_bfloat16 h0 = __float2bfloat16(w0);
        __nv_bfloat16 h1 = __float2bfloat16(w1);
        __nv_bfloat16 l0 = __float2bfloat16(w0 - __bfloat162float(h0));
        __nv_bfloat16 l1 = __float2bfloat16(w1 - __bfloat162float(h1));
        h[half] = (uint32_t)__bfloat16_as_ushort(h0) | ((uint32_t)__bfloat16_as_ushort(h1) << 16);
        l[half] = (uint32_t)__bfloat16_as_ushort(l0) | ((uint32_t)__bfloat16_as_ushort(l1) << 16);
    }
    g_Bfrag[idx] = make_uint4(h[0], h[1], l[0], l[1]);
}

__global__ __launch_bounds__(THREADS)
void dcn_kernel(const float* __restrict__ x,
                const float* __restrict__ offset,
                const float* __restrict__ mask,
                const float* __restrict__ bias,
                float* __restrict__ out) {
    extern __shared__ char smem[];
    const uint32_t sbase = smem_u32(smem);

    const int t    = threadIdx.x;
    const int wid  = t >> 5;
    const int lane = t & 31;
    const int tile = blockIdx.x;     // 0..71
    const int b    = blockIdx.y;
    const int px0  = tile * MPX;

    // ---- phase 0: bilinear params for 128 px x 9 taps ----
    {
        int4*   sidx = reinterpret_cast<int4*>(smem + PIDX_OFF);
        float4* swgt = reinterpret_cast<float4*>(smem + PWGT_OFF);
        const float* offb  = offset + (size_t)b * (2 * KK * NPX);
        const float* maskb = mask   + (size_t)b * (KK * NPX);
        for (int i = t; i < MPX * KK; i += THREADS) {
            const int p  = i / KK;
            const int k  = i - p * KK;
            const int pxg = px0 + p;
            const int ho = pxg / 96;
            const int wo = pxg - ho * 96;
            const int ky = k / 3;
            const int kx = k - ky * 3;

            const float off_y = offb[(2 * k + 0) * NPX + pxg];
            const float off_x = offb[(2 * k + 1) * NPX + pxg];
            const float m     = maskb[k * NPX + pxg];

            const float py = (float)(ho - 1 + ky) + off_y;
            const float px = (float)(wo - 1 + kx) + off_x;

            const float y0f = floorf(py);
            const float x0f = floorf(px);
            const int y0 = (int)y0f, x0 = (int)x0f;
            const float ly = py - y0f, lx = px - x0f;
            const float hy = 1.0f - ly, hx = 1.0f - lx;
            const int y1 = y0 + 1, x1 = x0 + 1;

            const float vy0 = (y0 >= 0 && y0 < HH) ? 1.0f : 0.0f;
            const float vy1 = (y1 >= 0 && y1 < HH) ? 1.0f : 0.0f;
            const float vx0 = (x0 >= 0 && x0 < WW) ? 1.0f : 0.0f;
            const float vx1 = (x1 >= 0 && x1 < WW) ? 1.0f : 0.0f;

            const int cy0 = min(max(y0, 0), HH - 1);
            const int cy1 = min(max(y1, 0), HH - 1);
            const int cx0 = min(max(x0, 0), WW - 1);
            const int cx1 = min(max(x1, 0), WW - 1);

            int4 id;
            id.x = cy0 * WW + cx0;
            id.y = cy0 * WW + cx1;
            id.z = cy1 * WW + cx0;
            id.w = cy1 * WW + cx1;

            float4 w4;
            w4.x = hy * hx * m * vy0 * vx0;
            w4.y = hy * lx * m * vy0 * vx1;
            w4.z = ly * hx * m * vy1 * vx0;
            w4.w = ly * lx * m * vy1 * vx1;

            sidx[i] = id;
            swgt[i] = w4;
        }
    }
    __syncthreads();

    const float* xb0 = x + (size_t)b * CC * HW;
    const int4*   sidx = reinterpret_cast<const int4*>(smem + PIDX_OFF);
    const float4* swgt = reinterpret_cast<const float4*>(smem + PWGT_OFF);

    // warp tile coordinates: 4 M-tiles x 2 N-tiles of 32x32
    const int mbase = (wid & 3) * 32;     // pixel base within block tile
    const int ncol  = wid >> 2;           // 0..1 -> output base 32*ncol

    // fp32 accumulators: [mt 2][nt 4][4]
    float acc[2][4][4];
    #pragma unroll
    for (int mt = 0; mt < 2; mt++)
        #pragma unroll
        for (int nt = 0; nt < 4; nt++)
            #pragma unroll
            for (int q = 0; q < 4; q++) acc[mt][nt][q] = 0.0f;

    // ldmatrix per-lane addressing (row within 16, col half)
    const int arow  = lane & 15;
    const int acolb = (lane >> 4) * 16;

    for (int ch = 0; ch < CHUNKS; ch++) {
        // ---- fill A chunk: 128 px x 64 channels at tap ch (bf16 hi/lo, SW128) ----
        {
            char* ah = smem + A_HI_OFF;
            char* al = smem + A_LO_OFF;
            #pragma unroll
            for (int j = 0; j < 4; j++) {
                const int task = j * THREADS + t;
                const int p  = task & (MPX - 1);
                const int cg = task >> 7;            // channel group of 8
                const int4   id = sidx[p * KK + ch];
                const float4 w4 = swgt[p * KK + ch];
                const float* xb = xb0 + (size_t)(cg * 8) * HW;

                float v[8];
                #pragma unroll
                for (int cc2 = 0; cc2 < 8; cc2++) {
                    const float* xp = xb + cc2 * HW;
                    v[cc2] = w4.x * __ldg(xp + id.x)
                           + w4.y * __ldg(xp + id.y)
                           + w4.z * __ldg(xp + id.z)
                           + w4.w * __ldg(xp + id.w);
                }

                uint32_t hw[4], lw[4];
                #pragma unroll
                for (int q = 0; q < 4; q++) {
                    const float v0 = v[2 * q], v1 = v[2 * q + 1];
                    const __nv_bfloat16 h0 = __float2bfloat16(v0);
                    const __nv_bfloat16 h1 = __float2bfloat16(v1);
                    const __nv_bfloat16 l0 = __float2bfloat16(v0 - __bfloat162float(h0));
                    const __nv_bfloat16 l1 = __float2bfloat16(v1 - __bfloat162float(h1));
                    hw[q] = (uint32_t)__bfloat16_as_ushort(h0)
                          | ((uint32_t)__bfloat16_as_ushort(h1) << 16);
                    lw[q] = (uint32_t)__bfloat16_as_ushort(l0)
                          | ((uint32_t)__bfloat16_as_ushort(l1) << 16);
                }

                const uint32_t sw = sw128((uint32_t)(p * 128 + cg * 16));
                *reinterpret_cast<int4*>(ah + sw) = make_int4(hw[0], hw[1], hw[2], hw[3]);
                *reinterpret_cast<int4*>(al + sw) = make_int4(lw[0], lw[1], lw[2], lw[3]);
            }
        }
        __syncthreads();

        // ---- warp MMAs over this chunk: 4 k-steps x (2 mt x 4 nt) x 3 products ----
        const uint4* bfr = g_Bfrag + (size_t)(ch * KSTEPS) * 8 * 32;
        #pragma unroll
        for (int ks = 0; ks < KSTEPS; ks++) {
            // A fragments (hi & lo) for both M sub-tiles
            uint32_t ah0[4], ah1[4], al0[4], al1[4];
            {
                const uint32_t o0 = sw128((uint32_t)((mbase + arow) * 128      + ks * 32 + acolb));
                const uint32_t o1 = sw128((uint32_t)((mbase + 16 + arow) * 128 + ks * 32 + acolb));
                ldmatrix_x4(ah0[0], ah0[1], ah0[2], ah0[3], sbase + A_HI_OFF + o0);
                ldmatrix_x4(ah1[0], ah1[1], ah1[2], ah1[3], sbase + A_HI_OFF + o1);
                ldmatrix_x4(al0[0], al0[1], al0[2], al0[3], sbase + A_LO_OFF + o0);
                ldmatrix_x4(al1[0], al1[1], al1[2], al1[3], sbase + A_LO_OFF + o1);
            }
            // B fragments: 4 n-tiles, one LDG.128 each
            #pragma unroll
            for (int nt = 0; nt < 4; nt++) {
                const uint4 bf = __ldg(bfr + ((size_t)ks * 8 + (ncol * 4 + nt)) * 32 + lane);
                // Ahi * Bhi
                mma_bf16(acc[0][nt][0], acc[0][nt][1], acc[0][nt][2], acc[0][nt][3],
                         ah0[0], ah0[1], ah0[2], ah0[3], bf.x, bf.y);
                mma_bf16(acc[1][nt][0], acc[1][nt][1], acc[1][nt][2], acc[1][nt][3],
                         ah1[0], ah1[1], ah1[2], ah1[3], bf.x, bf.y);
                // Ahi * Blo
                mma_bf16(acc[0][nt][0], acc[0][nt][1], acc[0][nt][2], acc[0][nt][3],
                         ah0[0], ah0[1], ah0[2], ah0[3], bf.z, bf.w);
                mma_bf16(acc[1][nt][0], acc[1][nt][1], acc[1][nt][2], acc[1][nt][3],
                         ah1[0], ah1[1], ah1[2], ah1[3], bf.z, bf.w);
                // Alo * Bhi
                mma_bf16(acc[0][nt][0], acc[0][nt][1], acc[0][nt][2], acc[0][nt][3],
                         al0[0], al0[1], al0[2], al0[3], bf.x, bf.y);
                mma_bf16(acc[1][nt][0], acc[1][nt][1], acc[1][nt][2], acc[1][nt][3],
                         al1[0], al1[1], al1[2], al1[3], bf.x, bf.y);
            }
        }
        __syncthreads();   // before next chunk overwrites A
    }

    // ---- epilogue: transpose through smem (reuse param region), coalesced stores ----
    float* s_out = reinterpret_cast<float*>(smem + PIDX_OFF);   // [OO][SOUT_STRIDE]
    {
        const int g   = lane >> 2;
        const int tig = lane & 3;
        #pragma unroll
        for (int mt = 0; mt < 2; mt++) {
            #pragma unroll
            for (int nt = 0; nt < 4; nt++) {
                const int o  = ncol * 32 + nt * 8 + 2 * tig;
                const int p0 = mbase + mt * 16 + g;
                s_out[o * SOUT_STRIDE + p0]            = acc[mt][nt][0];
                s_out[(o + 1) * SOUT_STRIDE + p0]      = acc[mt][nt][1];
                s_out[o * SOUT_STRIDE + p0 + 8]        = acc[mt][nt][2];
                s_out[(o + 1) * SOUT_STRIDE + p0 + 8]  = acc[mt][nt][3];
            }
        }
    }
    __syncthreads();

    {
        float* ob = out + (size_t)b * OO * NPX + px0;
        #pragma unroll 8
        for (int i = 0; i < MPX * OO / THREADS; i++) {
            const int idx = i * THREADS + t;
            const int p = idx & (MPX - 1);
            const int o = idx >> 7;
            ob[(size_t)o * NPX + p] = s_out[o * SOUT_STRIDE + p] + __ldg(bias + o);
        }
    }
}

extern "C" void kernel_launch(void* const* d_in, const int* in_sizes, int n_in,
                              void* d_out, int out_size) {
    const float* x      = (const float*)d_in[0];
    const float* offset = (const float*)d_in[1];
    const float* mask   = (const float*)d_in[2];
    const float* weight = (const float*)d_in[3];
    const float* bias   = (const float*)d_in[4];
    float* out = (float*)d_out;

    prep_weight_kernel<<<(CHUNKS * KSTEPS * 8 * 32 + 255) / 256, 256>>>(weight);

    cudaFuncSetAttribute(dcn_kernel,
                         cudaFuncAttributeMaxDynamicSharedMemorySize, SMEM_TOTAL);

    dim3 grid(NPX / MPX, BB);   // (72, 4) = 288 blocks
    dcn_kernel<<<grid, THREADS, SMEM_TOTAL>>>(x, offset, mask, bias, out);
}

// round 10
// speedup vs baseline: 5.2627x; 1.4347x over previous
#include <cuda_runtime.h>
#include <cuda_bf16.h>
#include <cstdint>

// ModulatedDeformConv2d: B=4, C=64, H=W=96, O=64, 3x3, stride=1, pad=1, dil=1, DG=1.
#define BB 4
#define CC 64
#define HH 96
#define WW 96
#define OO 64
#define KK 9
#define HW (HH*WW)
#define NPX (96*96)         // 9216 output pixels per image
#define MPX 64              // pixels per block (GEMM M)
#define THREADS 256
#define CHUNKS 9            // one chunk per 3x3 tap, K=64 channels each
#define KSTEPS 4            // 64 / 16

// ---- shared memory: double-buffered A (bf16 hi/lo, SW128, 64 rows x 128B) ----
// buf s: hi @ s*16384, lo @ s*16384 + 8192. Epilogue reuses region from 0.
#define A_BUF(s)   ((s) * 16384)
#define A_LO       8192
#define SMEM_TOTAL 32768
#define SOUT_STRIDE 68      // epilogue s_out[o][p] stride in floats (conflict-free)

__device__ __forceinline__ uint32_t smem_u32(const void* p) {
    uint32_t a;
    asm("{ .reg .u64 t; cvta.to.shared.u64 t, %1; cvt.u32.u64 %0, t; }" : "=r"(a) : "l"(p));
    return a;
}
__device__ __forceinline__ uint32_t sw128(uint32_t off) {
    return off ^ ((off >> 3) & 0x70);
}

__device__ __forceinline__ void ldmatrix_x4(uint32_t &r0, uint32_t &r1,
                                            uint32_t &r2, uint32_t &r3, uint32_t addr) {
    asm volatile("ldmatrix.sync.aligned.m8n8.x4.shared.b16 {%0,%1,%2,%3}, [%4];"
                 : "=r"(r0), "=r"(r1), "=r"(r2), "=r"(r3) : "r"(addr));
}

__device__ __forceinline__ void mma_bf16(float &d0, float &d1, float &d2, float &d3,
                                         uint32_t a0, uint32_t a1, uint32_t a2, uint32_t a3,
                                         uint32_t b0, uint32_t b1) {
    asm volatile("mma.sync.aligned.m16n8k16.row.col.f32.bf16.bf16.f32 "
                 "{%0,%1,%2,%3}, {%4,%5,%6,%7}, {%8,%9}, {%0,%1,%2,%3};"
                 : "+f"(d0), "+f"(d1), "+f"(d2), "+f"(d3)
                 : "r"(a0), "r"(a1), "r"(a2), "r"(a3), "r"(b0), "r"(b1));
}

// Pre-packed B fragments, exact mma.sync lane order.
// Index: ((chunk*KSTEPS + kstep)*8 + ntile)*32 + lane -> {bhi0, bhi1, blo0, blo1}
__device__ __align__(16) uint4 g_Bfrag[CHUNKS * KSTEPS * 8 * 32];

__global__ void prep_weight_kernel(const float* __restrict__ weight) {
    const int idx = blockIdx.x * blockDim.x + threadIdx.x;   // 0 .. 9216-1
    if (idx >= CHUNKS * KSTEPS * 8 * 32) return;
    const int lane  = idx & 31;
    const int ntile = (idx >> 5) & 7;
    const int kstep = (idx >> 8) & 3;
    const int chunk = idx >> 10;

    const int n  = ntile * 8 + (lane >> 2);          // output channel o
    const int c0 = kstep * 16 + 2 * (lane & 3);      // input channel pair base

    uint32_t h[2], l[2];
    #pragma unroll
    for (int half = 0; half < 2; half++) {
        const int ca = c0 + half * 8;
        float w0 = weight[n * (CC * KK) + ca * KK + chunk];
        float w1 = weight[n * (CC * KK) + (ca + 1) * KK + chunk];
        __nv_bfloat16 h0 = __float2bfloat16(w0);
        __nv_bfloat16 h1 = __float2bfloat16(w1);
        __nv_bfloat16 l0 = __float2bfloat16(w0 - __bfloat162float(h0));
        __nv_bfloat16 l1 = __float2bfloat16(w1 - __bfloat162float(h1));
        h[half] = (uint32_t)__bfloat16_as_ushort(h0) | ((uint32_t)__bfloat16_as_ushort(h1) << 16);
        l[half] = (uint32_t)__bfloat16_as_ushort(l0) | ((uint32_t)__bfloat16_as_ushort(l1) << 16);
    }
    g_Bfrag[idx] = make_uint4(h[0], h[1], l[0], l[1]);
}

__global__ __launch_bounds__(THREADS, 4)
void dcn_kernel(const float* __restrict__ x,
                const float* __restrict__ offset,
                const float* __restrict__ mask,
                const float* __restrict__ bias,
                float* __restrict__ out) {
    extern __shared__ char smem[];
    const uint32_t sbase = smem_u32(smem);

    const int t    = threadIdx.x;
    const int wid  = t >> 5;
    const int lane = t & 31;
    const int tile = blockIdx.x;     // 0..143
    const int b    = blockIdx.y;
    const int px0  = tile * MPX;

    // sampling role: pixel p (shared by 4 warps), channel groups cg0*16..+15
    const int sp   = t & 63;                 // pixel within tile
    const int cg0  = t >> 6;                 // 0..3 -> channels cg0*16 and cg0*16+64... (two int4 groups)
    const int pxg  = px0 + sp;
    const int ho   = pxg / 96;
    const int wo   = pxg - ho * 96;

    // warp tile: 4 M-rows x 2 N-cols of 16x32
    const int mbase = (wid & 3) * 16;
    const int ncol  = wid >> 2;

    const float* xb0  = x + (size_t)b * CC * HW;
    const float* offb = offset + (size_t)b * (2 * KK * NPX) + pxg;
    const float* mskb = mask   + (size_t)b * (KK * NPX) + pxg;

    float acc[4][4];
    #pragma unroll
    for (int nt = 0; nt < 4; nt++)
        #pragma unroll
        for (int q = 0; q < 4; q++) acc[nt][q] = 0.0f;

    const int arow  = lane & 15;
    const int acolb = (lane >> 4) * 16;

    for (int ch = 0; ch < CHUNKS; ch++) {
        const int s = ch & 1;

        // ---- fill A[s]: 64 px x 64 channels at tap ch ----
        {
            // per-pixel bilinear params for this tap (computed inline, 4x redundant)
            const float off_y = __ldg(offb + (2 * ch + 0) * NPX);
            const float off_x = __ldg(offb + (2 * ch + 1) * NPX);
            const float m     = __ldg(mskb + ch * NPX);

            const int ky = ch / 3;
            const int kx = ch - ky * 3;
            const float py = (float)(ho - 1 + ky) + off_y;
            const float px = (float)(wo - 1 + kx) + off_x;

            const float y0f = floorf(py);
            const float x0f = floorf(px);
            const int y0 = (int)y0f, x0 = (int)x0f;
            const float ly = py - y0f, lx = px - x0f;
            const float hy = 1.0f - ly, hx = 1.0f - lx;
            const int y1 = y0 + 1, x1 = x0 + 1;

            const float vy0 = (y0 >= 0 && y0 < HH) ? 1.0f : 0.0f;
            const float vy1 = (y1 >= 0 && y1 < HH) ? 1.0f : 0.0f;
            const float vx0 = (x0 >= 0 && x0 < WW) ? 1.0f : 0.0f;
            const float vx1 = (x1 >= 0 && x1 < WW) ? 1.0f : 0.0f;

            const int cy0 = min(max(y0, 0), HH - 1);
            const int cy1 = min(max(y1, 0), HH - 1);
            const int cx0 = min(max(x0, 0), WW - 1);
            const int cx1 = min(max(x1, 0), WW - 1);

            const int i00 = cy0 * WW + cx0;
            const int i01 = cy0 * WW + cx1;
            const int i10 = cy1 * WW + cx0;
            const int i11 = cy1 * WW + cx1;

            const float w00 = hy * hx * m * vy0 * vx0;
            const float w01 = hy * lx * m * vy0 * vx1;
            const float w10 = ly * hx * m * vy1 * vx0;
            const float w11 = ly * lx * m * vy1 * vx1;

            char* ah = smem + A_BUF(s);
            char* al = smem + A_BUF(s) + A_LO;

            #pragma unroll
            for (int g = 0; g < 2; g++) {              // two channel groups of 8
                const int cgi = cg0 + g * 4;           // 0..7
                const float* xb = xb0 + (size_t)(cgi * 8) * HW;

                float v[8];
                #pragma unroll
                for (int cc2 = 0; cc2 < 8; cc2++) {
                    const float* xp = xb + cc2 * HW;
                    v[cc2] = w00 * __ldg(xp + i00)
                           + w01 * __ldg(xp + i01)
                           + w10 * __ldg(xp + i10)
                           + w11 * __ldg(xp + i11);
                }

                uint32_t hw[4], lw[4];
                #pragma unroll
                for (int q = 0; q < 4; q++) {
                    const float v0 = v[2 * q], v1 = v[2 * q + 1];
                    const __nv_bfloat16 h0 = __float2bfloat16(v0);
                    const __nv_bfloat16 h1 = __float2bfloat16(v1);
                    const __nv_bfloat16 l0 = __float2bfloat16(v0 - __bfloat162float(h0));
                    const __nv_bfloat16 l1 = __float2bfloat16(v1 - __bfloat162float(h1));
                    hw[q] = (uint32_t)__bfloat16_as_ushort(h0)
                          | ((uint32_t)__bfloat16_as_ushort(h1) << 16);
                    lw[q] = (uint32_t)__bfloat16_as_ushort(l0)
                          | ((uint32_t)__bfloat16_as_ushort(l1) << 16);
                }

                const uint32_t sw = sw128((uint32_t)(sp * 128 + cgi * 16));
                *reinterpret_cast<int4*>(ah + sw) = make_int4(hw[0], hw[1], hw[2], hw[3]);
                *reinterpret_cast<int4*>(al + sw) = make_int4(lw[0], lw[1], lw[2], lw[3]);
            }
        }
        __syncthreads();   // A[s] ready; also guarantees mma of ch-2 (same buffer) done

        // ---- warp MMAs: 4 k-steps x 4 n-tiles x 3 products on 16x32 tile ----
        const uint4* bfr = g_Bfrag + (size_t)(ch * KSTEPS) * 8 * 32;
        #pragma unroll
        for (int ks = 0; ks < KSTEPS; ks++) {
            uint32_t ah[4], al4[4];
            const uint32_t o0 = sw128((uint32_t)((mbase + arow) * 128 + ks * 32 + acolb));
            ldmatrix_x4(ah[0], ah[1], ah[2], ah[3], sbase + A_BUF(s) + o0);
            ldmatrix_x4(al4[0], al4[1], al4[2], al4[3], sbase + A_BUF(s) + A_LO + o0);

            #pragma unroll
            for (int nt = 0; nt < 4; nt++) {
                const uint4 bf = __ldg(bfr + ((size_t)ks * 8 + (ncol * 4 + nt)) * 32 + lane);
                mma_bf16(acc[nt][0], acc[nt][1], acc[nt][2], acc[nt][3],
                         ah[0], ah[1], ah[2], ah[3], bf.x, bf.y);    // Ahi*Bhi
                mma_bf16(acc[nt][0], acc[nt][1], acc[nt][2], acc[nt][3],
                         ah[0], ah[1], ah[2], ah[3], bf.z, bf.w);    // Ahi*Blo
                mma_bf16(acc[nt][0], acc[nt][1], acc[nt][2], acc[nt][3],
                         al4[0], al4[1], al4[2], al4[3], bf.x, bf.y); // Alo*Bhi
            }
        }
        // no trailing sync: next fill targets the other buffer
    }

    __syncthreads();   // all ldmatrix reads done before epilogue overwrites smem

    // ---- epilogue: transpose through smem, coalesced stores ----
    float* s_out = reinterpret_cast<float*>(smem);   // [OO][SOUT_STRIDE]
    {
        const int g   = lane >> 2;
        const int tig = lane & 3;
        #pragma unroll
        for (int nt = 0; nt < 4; nt++) {
            const int o  = ncol * 32 + nt * 8 + 2 * tig;
            const int p0 = mbase + g;
            s_out[o * SOUT_STRIDE + p0]            = acc[nt][0];
            s_out[(o + 1) * SOUT_STRIDE + p0]      = acc[nt][1];
            s_out[o * SOUT_STRIDE + p0 + 8]        = acc[nt][2];
            s_out[(o + 1) * SOUT_STRIDE + p0 + 8]  = acc[nt][3];
        }
    }
    __syncthreads();

    {
        float* ob = out + (size_t)b * OO * NPX + px0;
        #pragma unroll
        for (int i = 0; i < MPX * OO / THREADS; i++) {
            const int idx = i * THREADS + t;
            const int p = idx & (MPX - 1);
            const int o = idx >> 6;
            ob[(size_t)o * NPX + p] = s_out[o * SOUT_STRIDE + p] + __ldg(bias + o);
        }
    }
}

extern "C" void kernel_launch(void* const* d_in, const int* in_sizes, int n_in,
                              void* d_out, int out_size) {
    const float* x      = (const float*)d_in[0];
    const float* offset = (const float*)d_in[1];
    const float* mask   = (const float*)d_in[2];
    const float* weight = (const float*)d_in[3];
    const float* bias   = (const float*)d_in[4];
    float* out = (float*)d_out;

    prep_weight_kernel<<<(CHUNKS * KSTEPS * 8 * 32 + 255) / 256, 256>>>(weight);

    cudaFuncSetAttribute(dcn_kernel,
                         cudaFuncAttributeMaxDynamicSharedMemorySize, SMEM_TOTAL);

    dim3 grid(NPX / MPX, BB);   // (144, 4) = 576 blocks
    dcn_kernel<<<grid, THREADS, SMEM_TOTAL>>>(x, offset, mask, bias, out);
}

// round 11
// speedup vs baseline: 7.0301x; 1.3358x over previous
#include <cuda_runtime.h>
#include <cuda_bf16.h>
#include <cstdint>

// ModulatedDeformConv2d: B=4, C=64, H=W=96, O=64, 3x3, stride=1, pad=1, dil=1, DG=1.
#define BB 4
#define CC 64
#define HH 96
#define WW 96
#define OO 64
#define KK 9
#define HW (HH*WW)
#define NPX (96*96)         // 9216 output pixels per image
#define MPX 64              // pixels per block (GEMM M)
#define THREADS 256
#define CHUNKS 9
#define KSTEPS 4            // 64 / 16

// ---- shared memory ----
// A double buffer: buf s at s*16384 (hi), +8192 (lo). 64 rows x 128B, SW128.
#define A_BUF(s)   ((s) * 16384)
#define A_LO       8192
#define PIDX_OFF   32768                    // int4[576]   9216B
#define PWGT_OFF   (PIDX_OFF + 9216)        // float4[576] 9216B
#define SMEM_TOTAL (PWGT_OFF + 9216)        // 51200
#define SOUT_STRIDE 68

// NHWC copy of x: xt[b][hw][c]
__device__ __align__(16) float g_xt[BB * HW * CC];

__device__ __forceinline__ uint32_t smem_u32(const void* p) {
    uint32_t a;
    asm("{ .reg .u64 t; cvta.to.shared.u64 t, %1; cvt.u32.u64 %0, t; }" : "=r"(a) : "l"(p));
    return a;
}
__device__ __forceinline__ uint32_t sw128(uint32_t off) {
    return off ^ ((off >> 3) & 0x70);
}

__device__ __forceinline__ void ldmatrix_x4(uint32_t &r0, uint32_t &r1,
                                            uint32_t &r2, uint32_t &r3, uint32_t addr) {
    asm volatile("ldmatrix.sync.aligned.m8n8.x4.shared.b16 {%0,%1,%2,%3}, [%4];"
                 : "=r"(r0), "=r"(r1), "=r"(r2), "=r"(r3) : "r"(addr));
}

__device__ __forceinline__ void mma_bf16(float &d0, float &d1, float &d2, float &d3,
                                         uint32_t a0, uint32_t a1, uint32_t a2, uint32_t a3,
                                         uint32_t b0, uint32_t b1) {
    asm volatile("mma.sync.aligned.m16n8k16.row.col.f32.bf16.bf16.f32 "
                 "{%0,%1,%2,%3}, {%4,%5,%6,%7}, {%8,%9}, {%0,%1,%2,%3};"
                 : "+f"(d0), "+f"(d1), "+f"(d2), "+f"(d3)
                 : "r"(a0), "r"(a1), "r"(a2), "r"(a3), "r"(b0), "r"(b1));
}

// Pre-packed B fragments, exact mma.sync lane order.
__device__ __align__(16) uint4 g_Bfrag[CHUNKS * KSTEPS * 8 * 32];

__global__ void prep_weight_kernel(const float* __restrict__ weight) {
    const int idx = blockIdx.x * blockDim.x + threadIdx.x;
    if (idx >= CHUNKS * KSTEPS * 8 * 32) return;
    const int lane  = idx & 31;
    const int ntile = (idx >> 5) & 7;
    const int kstep = (idx >> 8) & 3;
    const int chunk = idx >> 10;

    const int n  = ntile * 8 + (lane >> 2);
    const int c0 = kstep * 16 + 2 * (lane & 3);

    uint32_t h[2], l[2];
    #pragma unroll
    for (int half = 0; half < 2; half++) {
        const int ca = c0 + half * 8;
        float w0 = weight[n * (CC * KK) + ca * KK + chunk];
        float w1 = weight[n * (CC * KK) + (ca + 1) * KK + chunk];
        __nv_bfloat16 h0 = __float2bfloat16(w0);
        __nv_bfloat16 h1 = __float2bfloat16(w1);
        __nv_bfloat16 l0 = __float2bfloat16(w0 - __bfloat162float(h0));
        __nv_bfloat16 l1 = __float2bfloat16(w1 - __bfloat162float(h1));
        h[half] = (uint32_t)__bfloat16_as_ushort(h0) | ((uint32_t)__bfloat16_as_ushort(h1) << 16);
        l[half] = (uint32_t)__bfloat16_as_ushort(l0) | ((uint32_t)__bfloat16_as_ushort(l1) << 16);
    }
    g_Bfrag[idx] = make_uint4(h[0], h[1], l[0], l[1]);
}

// Tiled NCHW -> NHWC transpose (coalesced both sides).
__global__ void prep_x_kernel(const float* __restrict__ x) {
    __shared__ float tile[32][33];
    const int bhw0 = blockIdx.x * 32;       // over B*HW, tile stays within one b (HW%32==0)
    const int c0   = blockIdx.y * 32;
    const int tx = threadIdx.x, ty = threadIdx.y;   // 32 x 8
    const int b   = bhw0 / HW;
    const int hwb = bhw0 - b * HW;
    #pragma unroll
    for (int j = 0; j < 4; j++) {
        const int c = c0 + ty + j * 8;
        tile[ty + j * 8][tx] = x[((size_t)b * CC + c) * HW + hwb + tx];
    }
    __syncthreads();
    #pragma unroll
    for (int j = 0; j < 4; j++) {
        const int hw = hwb + ty + j * 8;
        g_xt[((size_t)b * HW + hw) * CC + c0 + tx] = tile[tx][ty + j * 8];
    }
}

__global__ __launch_bounds__(THREADS, 4)
void dcn_kernel(const float* __restrict__ offset,
                const float* __restrict__ mask,
                const float* __restrict__ bias,
                float* __restrict__ out) {
    extern __shared__ char smem[];
    const uint32_t sbase = smem_u32(smem);

    const int t    = threadIdx.x;
    const int wid  = t >> 5;
    const int lane = t & 31;
    const int tile = blockIdx.x;     // 0..143
    const int b    = blockIdx.y;
    const int px0  = tile * MPX;

    // ---- phase 0: bilinear params for 64 px x 9 taps ----
    {
        int4*   sidx = reinterpret_cast<int4*>(smem + PIDX_OFF);
        float4* swgt = reinterpret_cast<float4*>(smem + PWGT_OFF);
        const float* offb  = offset + (size_t)b * (2 * KK * NPX);
        const float* maskb = mask   + (size_t)b * (KK * NPX);
        for (int i = t; i < MPX * KK; i += THREADS) {
            const int p  = i / KK;
            const int k  = i - p * KK;
            const int pxg = px0 + p;
            const int ho = pxg / 96;
            const int wo = pxg - ho * 96;
            const int ky = k / 3;
            const int kx = k - ky * 3;

            const float off_y = __ldg(offb + (2 * k + 0) * NPX + pxg);
            const float off_x = __ldg(offb + (2 * k + 1) * NPX + pxg);
            const float m     = __ldg(maskb + k * NPX + pxg);

            const float py = (float)(ho - 1 + ky) + off_y;
            const float px = (float)(wo - 1 + kx) + off_x;

            const float y0f = floorf(py);
            const float x0f = floorf(px);
            const int y0 = (int)y0f, x0 = (int)x0f;
            const float ly = py - y0f, lx = px - x0f;
            const float hy = 1.0f - ly, hx = 1.0f - lx;
            const int y1 = y0 + 1, x1 = x0 + 1;

            const float vy0 = (y0 >= 0 && y0 < HH) ? 1.0f : 0.0f;
            const float vy1 = (y1 >= 0 && y1 < HH) ? 1.0f : 0.0f;
            const float vx0 = (x0 >= 0 && x0 < WW) ? 1.0f : 0.0f;
            const float vx1 = (x1 >= 0 && x1 < WW) ? 1.0f : 0.0f;

            const int cy0 = min(max(y0, 0), HH - 1);
            const int cy1 = min(max(y1, 0), HH - 1);
            const int cx0 = min(max(x0, 0), WW - 1);
            const int cx1 = min(max(x1, 0), WW - 1);

            int4 id;
            id.x = cy0 * WW + cx0;
            id.y = cy0 * WW + cx1;
            id.z = cy1 * WW + cx0;
            id.w = cy1 * WW + cx1;

            float4 w4;
            w4.x = hy * hx * m * vy0 * vx0;
            w4.y = hy * lx * m * vy0 * vx1;
            w4.z = ly * hx * m * vy1 * vx0;
            w4.w = ly * lx * m * vy1 * vx1;

            sidx[i] = id;
            swgt[i] = w4;
        }
    }
    __syncthreads();

    const int4*   sidx = reinterpret_cast<const int4*>(smem + PIDX_OFF);
    const float4* swgt = reinterpret_cast<const float4*>(smem + PWGT_OFF);
    // float2 view of xt for this image: element (spatial idx)*32 + lane = channels 2lane,2lane+1
    const float2* xt2 = reinterpret_cast<const float2*>(g_xt) + (size_t)b * HW * 32;

    // warp tile: 4 M-rows x 2 N-cols of 16x32
    const int mbase = (wid & 3) * 16;
    const int ncol  = wid >> 2;

    float acc[4][4];
    #pragma unroll
    for (int nt = 0; nt < 4; nt++)
        #pragma unroll
        for (int q = 0; q < 4; q++) acc[nt][q] = 0.0f;

    const int arow  = lane & 15;
    const int acolb = (lane >> 4) * 16;

    for (int ch = 0; ch < CHUNKS; ch++) {
        const int s = ch & 1;

        // ---- fill A[s]: warp = 8 pixels, lane = channel pair ----
        {
            char* ah = smem + A_BUF(s);
            char* al = smem + A_BUF(s) + A_LO;
            #pragma unroll
            for (int i = 0; i < 8; i++) {
                const int p = wid * 8 + i;
                const int4   id = sidx[p * KK + ch];
                const float4 w4 = swgt[p * KK + ch];

                const float2 v00 = __ldg(xt2 + (size_t)id.x * 32 + lane);
                const float2 v01 = __ldg(xt2 + (size_t)id.y * 32 + lane);
                const float2 v10 = __ldg(xt2 + (size_t)id.z * 32 + lane);
                const float2 v11 = __ldg(xt2 + (size_t)id.w * 32 + lane);

                const float vx = w4.x * v00.x + w4.y * v01.x + w4.z * v10.x + w4.w * v11.x;
                const float vy = w4.x * v00.y + w4.y * v01.y + w4.z * v10.y + w4.w * v11.y;

                const __nv_bfloat16 h0 = __float2bfloat16(vx);
                const __nv_bfloat16 h1 = __float2bfloat16(vy);
                const __nv_bfloat16 l0 = __float2bfloat16(vx - __bfloat162float(h0));
                const __nv_bfloat16 l1 = __float2bfloat16(vy - __bfloat162float(h1));
                const uint32_t hw_ = (uint32_t)__bfloat16_as_ushort(h0)
                                   | ((uint32_t)__bfloat16_as_ushort(h1) << 16);
                const uint32_t lw_ = (uint32_t)__bfloat16_as_ushort(l0)
                                   | ((uint32_t)__bfloat16_as_ushort(l1) << 16);

                const uint32_t sw = sw128((uint32_t)(p * 128 + lane * 4));
                *reinterpret_cast<uint32_t*>(ah + sw) = hw_;
                *reinterpret_cast<uint32_t*>(al + sw) = lw_;
            }
        }
        __syncthreads();   // A[s] ready; also proves mma on this buffer (ch-2) is done

        // ---- warp MMAs: 4 k-steps x 4 n-tiles x 3 products ----
        const uint4* bfr = g_Bfrag + (size_t)(ch * KSTEPS) * 8 * 32;
        #pragma unroll
        for (int ks = 0; ks < KSTEPS; ks++) {
            uint32_t ah[4], al4[4];
            const uint32_t o0 = sw128((uint32_t)((mbase + arow) * 128 + ks * 32 + acolb));
            ldmatrix_x4(ah[0], ah[1], ah[2], ah[3], sbase + A_BUF(s) + o0);
            ldmatrix_x4(al4[0], al4[1], al4[2], al4[3], sbase + A_BUF(s) + A_LO + o0);

            #pragma unroll
            for (int nt = 0; nt < 4; nt++) {
                const uint4 bf = __ldg(bfr + ((size_t)ks * 8 + (ncol * 4 + nt)) * 32 + lane);
                mma_bf16(acc[nt][0], acc[nt][1], acc[nt][2], acc[nt][3],
                         ah[0], ah[1], ah[2], ah[3], bf.x, bf.y);     // Ahi*Bhi
                mma_bf16(acc[nt][0], acc[nt][1], acc[nt][2], acc[nt][3],
                         ah[0], ah[1], ah[2], ah[3], bf.z, bf.w);     // Ahi*Blo
                mma_bf16(acc[nt][0], acc[nt][1], acc[nt][2], acc[nt][3],
                         al4[0], al4[1], al4[2], al4[3], bf.x, bf.y); // Alo*Bhi
            }
        }
    }

    __syncthreads();   // ldmatrix reads done before epilogue overwrites smem

    // ---- epilogue: transpose through smem, coalesced stores ----
    float* s_out = reinterpret_cast<float*>(smem);   // [OO][SOUT_STRIDE]
    {
        const int g   = lane >> 2;
        const int tig = lane & 3;
        #pragma unroll
        for (int nt = 0; nt < 4; nt++) {
            const int o  = ncol * 32 + nt * 8 + 2 * tig;
            const int p0 = mbase + g;
            s_out[o * SOUT_STRIDE + p0]            = acc[nt][0];
            s_out[(o + 1) * SOUT_STRIDE + p0]      = acc[nt][1];
            s_out[o * SOUT_STRIDE + p0 + 8]        = acc[nt][2];
            s_out[(o + 1) * SOUT_STRIDE + p0 + 8]  = acc[nt][3];
        }
    }
    __syncthreads();

    {
        float* ob = out + (size_t)b * OO * NPX + px0;
        #pragma unroll
        for (int i = 0; i < MPX * OO / THREADS; i++) {
            const int idx = i * THREADS + t;
            const int p = idx & (MPX - 1);
            const int o = idx >> 6;
            ob[(size_t)o * NPX + p] = s_out[o * SOUT_STRIDE + p] + __ldg(bias + o);
        }
    }
}

extern "C" void kernel_launch(void* const* d_in, const int* in_sizes, int n_in,
                              void* d_out, int out_size) {
    const float* x      = (const float*)d_in[0];
    const float* offset = (const float*)d_in[1];
    const float* mask   = (const float*)d_in[2];
    const float* weight = (const float*)d_in[3];
    const float* bias   = (const float*)d_in[4];
    float* out = (float*)d_out;

    prep_weight_kernel<<<(CHUNKS * KSTEPS * 8 * 32 + 255) / 256, 256>>>(weight);

    dim3 tgrid(BB * HW / 32, CC / 32);
    prep_x_kernel<<<tgrid, dim3(32, 8)>>>(x);

    cudaFuncSetAttribute(dcn_kernel,
                         cudaFuncAttributeMaxDynamicSharedMemorySize, SMEM_TOTAL);

    dim3 grid(NPX / MPX, BB);   // (144, 4) = 576 blocks
    dcn_kernel<<<grid, THREADS, SMEM_TOTAL>>>(offset, mask, bias, out);
}

// round 12
// speedup vs baseline: 7.2815x; 1.0358x over previous
#include <cuda_runtime.h>
#include <cuda_bf16.h>
#include <cuda_fp16.h>
#include <cstdint>

// ModulatedDeformConv2d: B=4, C=64, H=W=96, O=64, 3x3, stride=1, pad=1, dil=1, DG=1.
#define BB 4
#define CC 64
#define HH 96
#define WW 96
#define OO 64
#define KK 9
#define HW (HH*WW)
#define NPX (96*96)         // 9216 output pixels per image
#define MPX 64              // pixels per block (GEMM M)
#define THREADS 256
#define CHUNKS 9
#define KSTEPS 4            // 64 / 16

// ---- shared memory ----
#define A_BUF(s)   ((s) * 16384)
#define A_LO       8192
#define PIDX_OFF   32768                    // int4[576]   9216B
#define PWGT_OFF   (PIDX_OFF + 9216)        // float4[576] 9216B
#define SMEM_TOTAL (PWGT_OFF + 9216)        // 51200
#define SOUT_STRIDE 68

#define TRANS_BLOCKS (BB * HW / 32)         // 1152
#define WPREP_BLOCKS 36                     // 9216 threads

// NHWC fp16 copy of x: g_xh[b][hw][c]
__device__ __align__(16) __half g_xh[BB * HW * CC];
// Pre-packed B fragments, exact mma.sync lane order.
__device__ __align__(16) uint4 g_Bfrag[CHUNKS * KSTEPS * 8 * 32];

__device__ __forceinline__ uint32_t smem_u32(const void* p) {
    uint32_t a;
    asm("{ .reg .u64 t; cvta.to.shared.u64 t, %1; cvt.u32.u64 %0, t; }" : "=r"(a) : "l"(p));
    return a;
}
__device__ __forceinline__ uint32_t sw128(uint32_t off) {
    return off ^ ((off >> 3) & 0x70);
}

__device__ __forceinline__ void ldmatrix_x4(uint32_t &r0, uint32_t &r1,
                                            uint32_t &r2, uint32_t &r3, uint32_t addr) {
    asm volatile("ldmatrix.sync.aligned.m8n8.x4.shared.b16 {%0,%1,%2,%3}, [%4];"
                 : "=r"(r0), "=r"(r1), "=r"(r2), "=r"(r3) : "r"(addr));
}

__device__ __forceinline__ void mma_bf16(float &d0, float &d1, float &d2, float &d3,
                                         uint32_t a0, uint32_t a1, uint32_t a2, uint32_t a3,
                                         uint32_t b0, uint32_t b1) {
    asm volatile("mma.sync.aligned.m16n8k16.row.col.f32.bf16.bf16.f32 "
                 "{%0,%1,%2,%3}, {%4,%5,%6,%7}, {%8,%9}, {%0,%1,%2,%3};"
                 : "+f"(d0), "+f"(d1), "+f"(d2), "+f"(d3)
                 : "r"(a0), "r"(a1), "r"(a2), "r"(a3), "r"(b0), "r"(b1));
}

// ---- fused prep: NCHW->NHWC fp16 transpose (blocks 0..1151) + weight pack (blocks 1152..1187) ----
__global__ void prep_kernel(const float* __restrict__ x,
                            const float* __restrict__ weight) {
    if (blockIdx.x < TRANS_BLOCKS) {
        __shared__ float tile[CC][33];
        const int t    = threadIdx.x;
        const int bhw0 = blockIdx.x * 32;
        const int b    = bhw0 / HW;
        const int hwb  = bhw0 - b * HW;
        // read: 64 channels x 32 hw, coalesced over hw
        {
            const int tx = t & 31;          // hw
            const int c0 = t >> 5;          // 0..7
            #pragma unroll
            for (int j = 0; j < 8; j++) {
                const int c = c0 + j * 8;
                tile[c][tx] = x[((size_t)b * CC + c) * HW + hwb + tx];
            }
        }
        __syncthreads();
        // write: warp = one hw row, lanes = 32 channel pairs (128B coalesced)
        {
            const int cp  = t & 31;
            const int hl0 = t >> 5;         // 0..7
            __half2* xh2 = reinterpret_cast<__half2*>(g_xh);
            #pragma unroll
            for (int j = 0; j < 4; j++) {
                const int hl = hl0 + j * 8;
                const float2 v = make_float2(tile[2 * cp][hl], tile[2 * cp + 1][hl]);
                xh2[((size_t)b * HW + hwb + hl) * 32 + cp] = __float22half2_rn(v);
            }
        }
    } else {
        const int idx = (blockIdx.x - TRANS_BLOCKS) * blockDim.x + threadIdx.x;
        if (idx >= CHUNKS * KSTEPS * 8 * 32) return;
        const int lane  = idx & 31;
        const int ntile = (idx >> 5) & 7;
        const int kstep = (idx >> 8) & 3;
        const int chunk = idx >> 10;

        const int n  = ntile * 8 + (lane >> 2);
        const int c0 = kstep * 16 + 2 * (lane & 3);

        uint32_t h[2], l[2];
        #pragma unroll
        for (int half = 0; half < 2; half++) {
            const int ca = c0 + half * 8;
            float w0 = weight[n * (CC * KK) + ca * KK + chunk];
            float w1 = weight[n * (CC * KK) + (ca + 1) * KK + chunk];
            __nv_bfloat16 h0 = __float2bfloat16(w0);
            __nv_bfloat16 h1 = __float2bfloat16(w1);
            __nv_bfloat16 l0 = __float2bfloat16(w0 - __bfloat162float(h0));
            __nv_bfloat16 l1 = __float2bfloat16(w1 - __bfloat162float(h1));
            h[half] = (uint32_t)__bfloat16_as_ushort(h0) | ((uint32_t)__bfloat16_as_ushort(h1) << 16);
            l[half] = (uint32_t)__bfloat16_as_ushort(l0) | ((uint32_t)__bfloat16_as_ushort(l1) << 16);
        }
        g_Bfrag[idx] = make_uint4(h[0], h[1], l[0], l[1]);
    }
}

__global__ __launch_bounds__(THREADS, 4)
void dcn_kernel(const float* __restrict__ offset,
                const float* __restrict__ mask,
                const float* __restrict__ bias,
                float* __restrict__ out) {
    extern __shared__ char smem[];
    const uint32_t sbase = smem_u32(smem);

    const int t    = threadIdx.x;
    const int wid  = t >> 5;
    const int lane = t & 31;
    const int tile = blockIdx.x;     // 0..143
    const int b    = blockIdx.y;
    const int px0  = tile * MPX;

    // ---- phase 0: bilinear params for 64 px x 9 taps ----
    {
        int4*   sidx = reinterpret_cast<int4*>(smem + PIDX_OFF);
        float4* swgt = reinterpret_cast<float4*>(smem + PWGT_OFF);
        const float* offb  = offset + (size_t)b * (2 * KK * NPX);
        const float* maskb = mask   + (size_t)b * (KK * NPX);
        for (int i = t; i < MPX * KK; i += THREADS) {
            const int p  = i / KK;
            const int k  = i - p * KK;
            const int pxg = px0 + p;
            const int ho = pxg / 96;
            const int wo = pxg - ho * 96;
            const int ky = k / 3;
            const int kx = k - ky * 3;

            const float off_y = __ldg(offb + (2 * k + 0) * NPX + pxg);
            const float off_x = __ldg(offb + (2 * k + 1) * NPX + pxg);
            const float m     = __ldg(maskb + k * NPX + pxg);

            const float py = (float)(ho - 1 + ky) + off_y;
            const float px = (float)(wo - 1 + kx) + off_x;

            const float y0f = floorf(py);
            const float x0f = floorf(px);
            const int y0 = (int)y0f, x0 = (int)x0f;
            const float ly = py - y0f, lx = px - x0f;
            const float hy = 1.0f - ly, hx = 1.0f - lx;
            const int y1 = y0 + 1, x1 = x0 + 1;

            const float vy0 = (y0 >= 0 && y0 < HH) ? 1.0f : 0.0f;
            const float vy1 = (y1 >= 0 && y1 < HH) ? 1.0f : 0.0f;
            const float vx0 = (x0 >= 0 && x0 < WW) ? 1.0f : 0.0f;
            const float vx1 = (x1 >= 0 && x1 < WW) ? 1.0f : 0.0f;

            const int cy0 = min(max(y0, 0), HH - 1);
            const int cy1 = min(max(y1, 0), HH - 1);
            const int cx0 = min(max(x0, 0), WW - 1);
            const int cx1 = min(max(x1, 0), WW - 1);

            int4 id;
            id.x = cy0 * WW + cx0;
            id.y = cy0 * WW + cx1;
            id.z = cy1 * WW + cx0;
            id.w = cy1 * WW + cx1;

            float4 w4;
            w4.x = hy * hx * m * vy0 * vx0;
            w4.y = hy * lx * m * vy0 * vx1;
            w4.z = ly * hx * m * vy1 * vx0;
            w4.w = ly * lx * m * vy1 * vx1;

            sidx[i] = id;
            swgt[i] = w4;
        }
    }
    __syncthreads();

    const int4*   sidx = reinterpret_cast<const int4*>(smem + PIDX_OFF);
    const float4* swgt = reinterpret_cast<const float4*>(smem + PWGT_OFF);
    // __half2 view: element (spatial idx)*32 + lane = channels 2lane, 2lane+1
    const __half2* xh2 = reinterpret_cast<const __half2*>(g_xh) + (size_t)b * HW * 32;

    // warp tile: 4 M-rows x 2 N-cols of 16x32
    const int mbase = (wid & 3) * 16;
    const int ncol  = wid >> 2;

    float acc[4][4];
    #pragma unroll
    for (int nt = 0; nt < 4; nt++)
        #pragma unroll
        for (int q = 0; q < 4; q++) acc[nt][q] = 0.0f;

    const int arow  = lane & 15;
    const int acolb = (lane >> 4) * 16;

    for (int ch = 0; ch < CHUNKS; ch++) {
        const int s = ch & 1;

        // ---- fill A[s]: warp = 8 pixels, lane = channel pair (fp16 source) ----
        {
            char* ah = smem + A_BUF(s);
            char* al = smem + A_BUF(s) + A_LO;
            #pragma unroll
            for (int i = 0; i < 8; i++) {
                const int p = wid * 8 + i;
                const int4   id = sidx[p * KK + ch];
                const float4 w4 = swgt[p * KK + ch];

                const float2 v00 = __half22float2(__ldg(xh2 + (size_t)id.x * 32 + lane));
                const float2 v01 = __half22float2(__ldg(xh2 + (size_t)id.y * 32 + lane));
                const float2 v10 = __half22float2(__ldg(xh2 + (size_t)id.z * 32 + lane));
                const float2 v11 = __half22float2(__ldg(xh2 + (size_t)id.w * 32 + lane));

                const float vx = w4.x * v00.x + w4.y * v01.x + w4.z * v10.x + w4.w * v11.x;
                const float vy = w4.x * v00.y + w4.y * v01.y + w4.z * v10.y + w4.w * v11.y;

                const __nv_bfloat16 h0 = __float2bfloat16(vx);
                const __nv_bfloat16 h1 = __float2bfloat16(vy);
                const __nv_bfloat16 l0 = __float2bfloat16(vx - __bfloat162float(h0));
                const __nv_bfloat16 l1 = __float2bfloat16(vy - __bfloat162float(h1));
                const uint32_t hw_ = (uint32_t)__bfloat16_as_ushort(h0)
                                   | ((uint32_t)__bfloat16_as_ushort(h1) << 16);
                const uint32_t lw_ = (uint32_t)__bfloat16_as_ushort(l0)
                                   | ((uint32_t)__bfloat16_as_ushort(l1) << 16);

                const uint32_t sw = sw128((uint32_t)(p * 128 + lane * 4));
                *reinterpret_cast<uint32_t*>(ah + sw) = hw_;
                *reinterpret_cast<uint32_t*>(al + sw) = lw_;
            }
        }
        __syncthreads();   // A[s] ready; also proves mma on this buffer (ch-2) is done

        // ---- warp MMAs: 4 k-steps x 4 n-tiles x 3 products ----
        const uint4* bfr = g_Bfrag + (size_t)(ch * KSTEPS) * 8 * 32;
        #pragma unroll
        for (int ks = 0; ks < KSTEPS; ks++) {
            uint32_t ah[4], al4[4];
            const uint32_t o0 = sw128((uint32_t)((mbase + arow) * 128 + ks * 32 + acolb));
            ldmatrix_x4(ah[0], ah[1], ah[2], ah[3], sbase + A_BUF(s) + o0);
            ldmatrix_x4(al4[0], al4[1], al4[2], al4[3], sbase + A_BUF(s) + A_LO + o0);

            #pragma unroll
            for (int nt = 0; nt < 4; nt++) {
                const uint4 bf = __ldg(bfr + ((size_t)ks * 8 + (ncol * 4 + nt)) * 32 + lane);
                mma_bf16(acc[nt][0], acc[nt][1], acc[nt][2], acc[nt][3],
                         ah[0], ah[1], ah[2], ah[3], bf.x, bf.y);     // Ahi*Bhi
                mma_bf16(acc[nt][0], acc[nt][1], acc[nt][2], acc[nt][3],
                         ah[0], ah[1], ah[2], ah[3], bf.z, bf.w);     // Ahi*Blo
                mma_bf16(acc[nt][0], acc[nt][1], acc[nt][2], acc[nt][3],
                         al4[0], al4[1], al4[2], al4[3], bf.x, bf.y); // Alo*Bhi
            }
        }
    }

    __syncthreads();   // ldmatrix reads done before epilogue overwrites smem

    // ---- epilogue: transpose through smem, coalesced stores ----
    float* s_out = reinterpret_cast<float*>(smem);   // [OO][SOUT_STRIDE]
    {
        const int g   = lane >> 2;
        const int tig = lane & 3;
        #pragma unroll
        for (int nt = 0; nt < 4; nt++) {
            const int o  = ncol * 32 + nt * 8 + 2 * tig;
            const int p0 = mbase + g;
            s_out[o * SOUT_STRIDE + p0]            = acc[nt][0];
            s_out[(o + 1) * SOUT_STRIDE + p0]      = acc[nt][1];
            s_out[o * SOUT_STRIDE + p0 + 8]        = acc[nt][2];
            s_out[(o + 1) * SOUT_STRIDE + p0 + 8]  = acc[nt][3];
        }
    }
    __syncthreads();

    {
        float* ob = out + (size_t)b * OO * NPX + px0;
        #pragma unroll
        for (int i = 0; i < MPX * OO / THREADS; i++) {
            const int idx = i * THREADS + t;
            const int p = idx & (MPX - 1);
            const int o = idx >> 6;
            ob[(size_t)o * NPX + p] = s_out[o * SOUT_STRIDE + p] + __ldg(bias + o);
        }
    }
}

extern "C" void kernel_launch(void* const* d_in, const int* in_sizes, int n_in,
                              void* d_out, int out_size) {
    const float* x      = (const float*)d_in[0];
    const float* offset = (const float*)d_in[1];
    const float* mask   = (const float*)d_in[2];
    const float* weight = (const float*)d_in[3];
    const float* bias   = (const float*)d_in[4];
    float* out = (float*)d_out;

    prep_kernel<<<TRANS_BLOCKS + WPREP_BLOCKS, 256>>>(x, weight);

    cudaFuncSetAttribute(dcn_kernel,
                         cudaFuncAttributeMaxDynamicSharedMemorySize, SMEM_TOTAL);

    dim3 grid(NPX / MPX, BB);   // (144, 4) = 576 blocks
    dcn_kernel<<<grid, THREADS, SMEM_TOTAL>>>(offset, mask, bias, out);
}

// round 13
// speedup vs baseline: 9.5230x; 1.3078x over previous
#include <cuda_runtime.h>
#include <cuda_fp16.h>
#include <cstdint>

// ModulatedDeformConv2d: B=4, C=64, H=W=96, O=64, 3x3, stride=1, pad=1, dil=1, DG=1.
#define BB 4
#define CC 64
#define HH 96
#define WW 96
#define OO 64
#define KK 9
#define HW (HH*WW)
#define NPX (96*96)         // 9216 output pixels per image
#define MPX 64              // pixels per block (GEMM M)
#define THREADS 256
#define CHUNKS 9
#define KSTEPS 4            // 64 / 16

// ---- shared memory ----
// A double buffer: fp16, 64 rows x 128B, SW128. buf s at s*8192.
#define A_BUF(s)   ((s) * 8192)
#define PIDX_OFF   16384                    // int4[576]   9216B
#define PWGT_OFF   (PIDX_OFF + 9216)        // float4[576] 9216B
#define SMEM_TOTAL (PWGT_OFF + 9216)        // 34816
#define SOUT_STRIDE 68                      // epilogue [OO][68] floats = 17408B (fits)

#define TRANS_BLOCKS (BB * HW / 32)         // 1152
#define WPREP_BLOCKS 36

// NHWC fp16 copy of x: g_xh[b][hw][c]
__device__ __align__(16) __half g_xh[BB * HW * CC];
// Pre-packed fp16 B fragments, exact mma.sync lane order: {b0, b1} per lane.
__device__ __align__(16) uint2 g_Bfrag[CHUNKS * KSTEPS * 8 * 32];

__device__ __forceinline__ uint32_t smem_u32(const void* p) {
    uint32_t a;
    asm("{ .reg .u64 t; cvta.to.shared.u64 t, %1; cvt.u32.u64 %0, t; }" : "=r"(a) : "l"(p));
    return a;
}
__device__ __forceinline__ uint32_t sw128(uint32_t off) {
    return off ^ ((off >> 3) & 0x70);
}

__device__ __forceinline__ void ldmatrix_x4(uint32_t &r0, uint32_t &r1,
                                            uint32_t &r2, uint32_t &r3, uint32_t addr) {
    asm volatile("ldmatrix.sync.aligned.m8n8.x4.shared.b16 {%0,%1,%2,%3}, [%4];"
                 : "=r"(r0), "=r"(r1), "=r"(r2), "=r"(r3) : "r"(addr));
}

__device__ __forceinline__ void mma_f16(float &d0, float &d1, float &d2, float &d3,
                                        uint32_t a0, uint32_t a1, uint32_t a2, uint32_t a3,
                                        uint32_t b0, uint32_t b1) {
    asm volatile("mma.sync.aligned.m16n8k16.row.col.f32.f16.f16.f32 "
                 "{%0,%1,%2,%3}, {%4,%5,%6,%7}, {%8,%9}, {%0,%1,%2,%3};"
                 : "+f"(d0), "+f"(d1), "+f"(d2), "+f"(d3)
                 : "r"(a0), "r"(a1), "r"(a2), "r"(a3), "r"(b0), "r"(b1));
}

// ---- fused prep: NCHW->NHWC fp16 transpose + fp16 weight fragment pack ----
__global__ void prep_kernel(const float* __restrict__ x,
                            const float* __restrict__ weight) {
    if (blockIdx.x < TRANS_BLOCKS) {
        __shared__ float tile[CC][33];
        const int t    = threadIdx.x;
        const int bhw0 = blockIdx.x * 32;
        const int b    = bhw0 / HW;
        const int hwb  = bhw0 - b * HW;
        {
            const int tx = t & 31;          // hw
            const int c0 = t >> 5;          // 0..7
            #pragma unroll
            for (int j = 0; j < 8; j++) {
                const int c = c0 + j * 8;
                tile[c][tx] = x[((size_t)b * CC + c) * HW + hwb + tx];
            }
        }
        __syncthreads();
        {
            const int cp  = t & 31;
            const int hl0 = t >> 5;
            __half2* xh2 = reinterpret_cast<__half2*>(g_xh);
            #pragma unroll
            for (int j = 0; j < 4; j++) {
                const int hl = hl0 + j * 8;
                const float2 v = make_float2(tile[2 * cp][hl], tile[2 * cp + 1][hl]);
                xh2[((size_t)b * HW + hwb + hl) * 32 + cp] = __float22half2_rn(v);
            }
        }
    } else {
        const int idx = (blockIdx.x - TRANS_BLOCKS) * blockDim.x + threadIdx.x;
        if (idx >= CHUNKS * KSTEPS * 8 * 32) return;
        const int lane  = idx & 31;
        const int ntile = (idx >> 5) & 7;
        const int kstep = (idx >> 8) & 3;
        const int chunk = idx >> 10;

        const int n  = ntile * 8 + (lane >> 2);
        const int c0 = kstep * 16 + 2 * (lane & 3);

        uint32_t hh[2];
        #pragma unroll
        for (int half = 0; half < 2; half++) {
            const int ca = c0 + half * 8;
            const float w0 = weight[n * (CC * KK) + ca * KK + chunk];
            const float w1 = weight[n * (CC * KK) + (ca + 1) * KK + chunk];
            const __half2 p = __float22half2_rn(make_float2(w0, w1));
            hh[half] = *reinterpret_cast<const uint32_t*>(&p);
        }
        g_Bfrag[idx] = make_uint2(hh[0], hh[1]);
    }
}

__global__ __launch_bounds__(THREADS, 4)
void dcn_kernel(const float* __restrict__ offset,
                const float* __restrict__ mask,
                const float* __restrict__ bias,
                float* __restrict__ out) {
    extern __shared__ char smem[];
    const uint32_t sbase = smem_u32(smem);

    const int t    = threadIdx.x;
    const int wid  = t >> 5;
    const int lane = t & 31;
    const int tile = blockIdx.x;     // 0..143
    const int b    = blockIdx.y;
    const int px0  = tile * MPX;

    // ---- phase 0: bilinear params for 64 px x 9 taps ----
    {
        int4*   sidx = reinterpret_cast<int4*>(smem + PIDX_OFF);
        float4* swgt = reinterpret_cast<float4*>(smem + PWGT_OFF);
        const float* offb  = offset + (size_t)b * (2 * KK * NPX);
        const float* maskb = mask   + (size_t)b * (KK * NPX);
        for (int i = t; i < MPX * KK; i += THREADS) {
            const int p  = i / KK;
            const int k  = i - p * KK;
            const int pxg = px0 + p;
            const int ho = pxg / 96;
            const int wo = pxg - ho * 96;
            const int ky = k / 3;
            const int kx = k - ky * 3;

            const float off_y = __ldg(offb + (2 * k + 0) * NPX + pxg);
            const float off_x = __ldg(offb + (2 * k + 1) * NPX + pxg);
            const float m     = __ldg(maskb + k * NPX + pxg);

            const float py = (float)(ho - 1 + ky) + off_y;
            const float px = (float)(wo - 1 + kx) + off_x;

            const float y0f = floorf(py);
            const float x0f = floorf(px);
            const int y0 = (int)y0f, x0 = (int)x0f;
            const float ly = py - y0f, lx = px - x0f;
            const float hy = 1.0f - ly, hx = 1.0f - lx;
            const int y1 = y0 + 1, x1 = x0 + 1;

            const float vy0 = (y0 >= 0 && y0 < HH) ? 1.0f : 0.0f;
            const float vy1 = (y1 >= 0 && y1 < HH) ? 1.0f : 0.0f;
            const float vx0 = (x0 >= 0 && x0 < WW) ? 1.0f : 0.0f;
            const float vx1 = (x1 >= 0 && x1 < WW) ? 1.0f : 0.0f;

            const int cy0 = min(max(y0, 0), HH - 1);
            const int cy1 = min(max(y1, 0), HH - 1);
            const int cx0 = min(max(x0, 0), WW - 1);
            const int cx1 = min(max(x1, 0), WW - 1);

            int4 id;
            id.x = cy0 * WW + cx0;
            id.y = cy0 * WW + cx1;
            id.z = cy1 * WW + cx0;
            id.w = cy1 * WW + cx1;

            float4 w4;
            w4.x = hy * hx * m * vy0 * vx0;
            w4.y = hy * lx * m * vy0 * vx1;
            w4.z = ly * hx * m * vy1 * vx0;
            w4.w = ly * lx * m * vy1 * vx1;

            sidx[i] = id;
            swgt[i] = w4;
        }
    }
    __syncthreads();

    const int4*   sidx = reinterpret_cast<const int4*>(smem + PIDX_OFF);
    const float4* swgt = reinterpret_cast<const float4*>(smem + PWGT_OFF);
    const __half2* xh2 = reinterpret_cast<const __half2*>(g_xh) + (size_t)b * HW * 32;

    // warp tile: 4 M-rows x 2 N-cols of 16x32
    const int mbase = (wid & 3) * 16;
    const int ncol  = wid >> 2;

    float acc[4][4];
    #pragma unroll
    for (int nt = 0; nt < 4; nt++)
        #pragma unroll
        for (int q = 0; q < 4; q++) acc[nt][q] = 0.0f;

    const int arow  = lane & 15;
    const int acolb = (lane >> 4) * 16;

    for (int ch = 0; ch < CHUNKS; ch++) {
        const int s = ch & 1;

        // ---- fill A[s]: warp = 8 pixels, lane = channel pair (fp16) ----
        {
            char* ah = smem + A_BUF(s);
            #pragma unroll
            for (int i = 0; i < 8; i++) {
                const int p = wid * 8 + i;
                const int4   id = sidx[p * KK + ch];
                const float4 w4 = swgt[p * KK + ch];

                const float2 v00 = __half22float2(__ldg(xh2 + (size_t)id.x * 32 + lane));
                const float2 v01 = __half22float2(__ldg(xh2 + (size_t)id.y * 32 + lane));
                const float2 v10 = __half22float2(__ldg(xh2 + (size_t)id.z * 32 + lane));
                const float2 v11 = __half22float2(__ldg(xh2 + (size_t)id.w * 32 + lane));

                const float vx = w4.x * v00.x + w4.y * v01.x + w4.z * v10.x + w4.w * v11.x;
                const float vy = w4.x * v00.y + w4.y * v01.y + w4.z * v10.y + w4.w * v11.y;

                const __half2 hv = __float22half2_rn(make_float2(vx, vy));
                const uint32_t sw = sw128((uint32_t)(p * 128 + lane * 4));
                *reinterpret_cast<uint32_t*>(ah + sw) = *reinterpret_cast<const uint32_t*>(&hv);
            }
        }
        __syncthreads();   // A[s] ready; also proves mma on this buffer (ch-2) is done

        // ---- warp MMAs: 4 k-steps x 4 n-tiles, single fp16 product ----
        const uint2* bfr = g_Bfrag + (size_t)(ch * KSTEPS) * 8 * 32;
        #pragma unroll
        for (int ks = 0; ks < KSTEPS; ks++) {
            uint32_t af[4];
            const uint32_t o0 = sw128((uint32_t)((mbase + arow) * 128 + ks * 32 + acolb));
            ldmatrix_x4(af[0], af[1], af[2], af[3], sbase + A_BUF(s) + o0);

            #pragma unroll
            for (int nt = 0; nt < 4; nt++) {
                const uint2 bf = __ldg(bfr + ((size_t)ks * 8 + (ncol * 4 + nt)) * 32 + lane);
                mma_f16(acc[nt][0], acc[nt][1], acc[nt][2], acc[nt][3],
                        af[0], af[1], af[2], af[3], bf.x, bf.y);
            }
        }
    }

    __syncthreads();   // ldmatrix reads done before epilogue overwrites smem

    // ---- epilogue: transpose through smem, coalesced stores ----
    float* s_out = reinterpret_cast<float*>(smem);   // [OO][SOUT_STRIDE]
    {
        const int g   = lane >> 2;
        const int tig = lane & 3;
        #pragma unroll
        for (int nt = 0; nt < 4; nt++) {
            const int o  = ncol * 32 + nt * 8 + 2 * tig;
            const int p0 = mbase + g;
            s_out[o * SOUT_STRIDE + p0]            = acc[nt][0];
            s_out[(o + 1) * SOUT_STRIDE + p0]      = acc[nt][1];
            s_out[o * SOUT_STRIDE + p0 + 8]        = acc[nt][2];
            s_out[(o + 1) * SOUT_STRIDE + p0 + 8]  = acc[nt][3];
        }
    }
    __syncthreads();

    {
        float* ob = out + (size_t)b * OO * NPX + px0;
        #pragma unroll
        for (int i = 0; i < MPX * OO / THREADS; i++) {
            const int idx = i * THREADS + t;
            const int p = idx & (MPX - 1);
            const int o = idx >> 6;
            ob[(size_t)o * NPX + p] = s_out[o * SOUT_STRIDE + p] + __ldg(bias + o);
        }
    }
}

extern "C" void kernel_launch(void* const* d_in, const int* in_sizes, int n_in,
                              void* d_out, int out_size) {
    const float* x      = (const float*)d_in[0];
    const float* offset = (const float*)d_in[1];
    const float* mask   = (const float*)d_in[2];
    const float* weight = (const float*)d_in[3];
    const float* bias   = (const float*)d_in[4];
    float* out = (float*)d_out;

    prep_kernel<<<TRANS_BLOCKS + WPREP_BLOCKS, 256>>>(x, weight);

    cudaFuncSetAttribute(dcn_kernel,
                         cudaFuncAttributeMaxDynamicSharedMemorySize, SMEM_TOTAL);

    dim3 grid(NPX / MPX, BB);   // (144, 4) = 576 blocks
    dcn_kernel<<<grid, THREADS, SMEM_TOTAL>>>(offset, mask, bias, out);
}

// round 14
// speedup vs baseline: 10.1995x; 1.0710x over previous
#include <cuda_runtime.h>
#include <cuda_fp16.h>
#include <cstdint>

// ModulatedDeformConv2d: B=4, C=64, H=W=96, O=64, 3x3, stride=1, pad=1, dil=1, DG=1.
#define BB 4
#define CC 64
#define HH 96
#define WW 96
#define OO 64
#define KK 9
#define HW (HH*WW)
#define NPX (96*96)         // 9216 output pixels per image
#define MPX 64              // pixels per block (GEMM M)
#define THREADS 256
#define CHUNKS 9
#define KSTEPS 4            // 64 / 16

// ---- shared memory ----
// A double buffer: fp16, 64 rows x 128B, SW128. buf s at s*8192.
#define A_BUF(s)   ((s) * 8192)
#define PIDX_OFF   16384                    // int4[576]  9216B (corner indices)
#define PWGT_OFF   (PIDX_OFF + 9216)        // int4[576]  9216B (4 x dup-half2 weights)
#define SMEM_TOTAL (PWGT_OFF + 9216)        // 34816
#define SOUT_STRIDE 68                      // epilogue [OO][68] floats (17408B, fits)

#define TRANS_BLOCKS (BB * HW / 96)         // 384 (each handles 3 sub-tiles of 32 hw)
#define WPREP_BLOCKS 36

// NHWC fp16 copy of x: g_xh[b][hw][c]
__device__ __align__(16) __half g_xh[BB * HW * CC];
// Pre-packed fp16 B fragments, exact mma.sync lane order: {b0, b1} per lane.
__device__ __align__(16) uint2 g_Bfrag[CHUNKS * KSTEPS * 8 * 32];

__device__ __forceinline__ uint32_t smem_u32(const void* p) {
    uint32_t a;
    asm("{ .reg .u64 t; cvta.to.shared.u64 t, %1; cvt.u32.u64 %0, t; }" : "=r"(a) : "l"(p));
    return a;
}
__device__ __forceinline__ uint32_t sw128(uint32_t off) {
    return off ^ ((off >> 3) & 0x70);
}
__device__ __forceinline__ uint32_t dup_h2(float w) {
    const __half2 h = __half2half2(__float2half_rn(w));
    return *reinterpret_cast<const uint32_t*>(&h);
}
__device__ __forceinline__ __half2 u2h2(uint32_t u) {
    return *reinterpret_cast<const __half2*>(&u);
}

__device__ __forceinline__ void ldmatrix_x4(uint32_t &r0, uint32_t &r1,
                                            uint32_t &r2, uint32_t &r3, uint32_t addr) {
    asm volatile("ldmatrix.sync.aligned.m8n8.x4.shared.b16 {%0,%1,%2,%3}, [%4];"
                 : "=r"(r0), "=r"(r1), "=r"(r2), "=r"(r3) : "r"(addr));
}

__device__ __forceinline__ void mma_f16(float &d0, float &d1, float &d2, float &d3,
                                        uint32_t a0, uint32_t a1, uint32_t a2, uint32_t a3,
                                        uint32_t b0, uint32_t b1) {
    asm volatile("mma.sync.aligned.m16n8k16.row.col.f32.f16.f16.f32 "
                 "{%0,%1,%2,%3}, {%4,%5,%6,%7}, {%8,%9}, {%0,%1,%2,%3};"
                 : "+f"(d0), "+f"(d1), "+f"(d2), "+f"(d3)
                 : "r"(a0), "r"(a1), "r"(a2), "r"(a3), "r"(b0), "r"(b1));
}

// ---- fused prep: NCHW->NHWC fp16 transpose (3 sub-tiles/block) + weight pack ----
__global__ void prep_kernel(const float* __restrict__ x,
                            const float* __restrict__ weight) {
    if (blockIdx.x < TRANS_BLOCKS) {
        __shared__ float tile[CC][33];
        const int t = threadIdx.x;
        #pragma unroll
        for (int sub = 0; sub < 3; sub++) {
            const int bhw0 = blockIdx.x * 96 + sub * 32;
            const int b    = bhw0 / HW;
            const int hwb  = bhw0 - b * HW;
            {
                const int tx = t & 31;          // hw
                const int c0 = t >> 5;          // 0..7
                #pragma unroll
                for (int j = 0; j < 8; j++) {
                    const int c = c0 + j * 8;
                    tile[c][tx] = x[((size_t)b * CC + c) * HW + hwb + tx];
                }
            }
            __syncthreads();
            {
                const int cp  = t & 31;
                const int hl0 = t >> 5;
                __half2* xh2 = reinterpret_cast<__half2*>(g_xh);
                #pragma unroll
                for (int j = 0; j < 4; j++) {
                    const int hl = hl0 + j * 8;
                    const float2 v = make_float2(tile[2 * cp][hl], tile[2 * cp + 1][hl]);
                    xh2[((size_t)b * HW + hwb + hl) * 32 + cp] = __float22half2_rn(v);
                }
            }
            __syncthreads();
        }
    } else {
        const int idx = (blockIdx.x - TRANS_BLOCKS) * blockDim.x + threadIdx.x;
        if (idx >= CHUNKS * KSTEPS * 8 * 32) return;
        const int lane  = idx & 31;
        const int ntile = (idx >> 5) & 7;
        const int kstep = (idx >> 8) & 3;
        const int chunk = idx >> 10;

        const int n  = ntile * 8 + (lane >> 2);
        const int c0 = kstep * 16 + 2 * (lane & 3);

        uint32_t hh[2];
        #pragma unroll
        for (int half = 0; half < 2; half++) {
            const int ca = c0 + half * 8;
            const float w0 = weight[n * (CC * KK) + ca * KK + chunk];
            const float w1 = weight[n * (CC * KK) + (ca + 1) * KK + chunk];
            const __half2 p = __float22half2_rn(make_float2(w0, w1));
            hh[half] = *reinterpret_cast<const uint32_t*>(&p);
        }
        g_Bfrag[idx] = make_uint2(hh[0], hh[1]);
    }
}

__global__ __launch_bounds__(THREADS, 4)
void dcn_kernel(const float* __restrict__ offset,
                const float* __restrict__ mask,
                const float* __restrict__ bias,
                float* __restrict__ out) {
    extern __shared__ char smem[];
    const uint32_t sbase = smem_u32(smem);

    const int t    = threadIdx.x;
    const int wid  = t >> 5;
    const int lane = t & 31;
    const int tile = blockIdx.x;     // 0..143
    const int b    = blockIdx.y;
    const int px0  = tile * MPX;

    // ---- phase 0: bilinear params for 64 px x 9 taps ----
    {
        int4* sidx = reinterpret_cast<int4*>(smem + PIDX_OFF);
        int4* swgt = reinterpret_cast<int4*>(smem + PWGT_OFF);
        const float* offb  = offset + (size_t)b * (2 * KK * NPX);
        const float* maskb = mask   + (size_t)b * (KK * NPX);
        for (int i = t; i < MPX * KK; i += THREADS) {
            const int p  = i / KK;
            const int k  = i - p * KK;
            const int pxg = px0 + p;
            const int ho = pxg / 96;
            const int wo = pxg - ho * 96;
            const int ky = k / 3;
            const int kx = k - ky * 3;

            const float off_y = __ldg(offb + (2 * k + 0) * NPX + pxg);
            const float off_x = __ldg(offb + (2 * k + 1) * NPX + pxg);
            const float m     = __ldg(maskb + k * NPX + pxg);

            const float py = (float)(ho - 1 + ky) + off_y;
            const float px = (float)(wo - 1 + kx) + off_x;

            const float y0f = floorf(py);
            const float x0f = floorf(px);
            const int y0 = (int)y0f, x0 = (int)x0f;
            const float ly = py - y0f, lx = px - x0f;
            const float hy = 1.0f - ly, hx = 1.0f - lx;
            const int y1 = y0 + 1, x1 = x0 + 1;

            const float vy0 = (y0 >= 0 && y0 < HH) ? 1.0f : 0.0f;
            const float vy1 = (y1 >= 0 && y1 < HH) ? 1.0f : 0.0f;
            const float vx0 = (x0 >= 0 && x0 < WW) ? 1.0f : 0.0f;
            const float vx1 = (x1 >= 0 && x1 < WW) ? 1.0f : 0.0f;

            const int cy0 = min(max(y0, 0), HH - 1);
            const int cy1 = min(max(y1, 0), HH - 1);
            const int cx0 = min(max(x0, 0), WW - 1);
            const int cx1 = min(max(x1, 0), WW - 1);

            int4 id;
            id.x = cy0 * WW + cx0;
            id.y = cy0 * WW + cx1;
            id.z = cy1 * WW + cx0;
            id.w = cy1 * WW + cx1;

            int4 wp;
            wp.x = (int)dup_h2(hy * hx * m * vy0 * vx0);
            wp.y = (int)dup_h2(hy * lx * m * vy0 * vx1);
            wp.z = (int)dup_h2(ly * hx * m * vy1 * vx0);
            wp.w = (int)dup_h2(ly * lx * m * vy1 * vx1);

            sidx[i] = id;
            swgt[i] = wp;
        }
    }
    __syncthreads();

    const int4* sidx = reinterpret_cast<const int4*>(smem + PIDX_OFF);
    const int4* swgt = reinterpret_cast<const int4*>(smem + PWGT_OFF);
    const __half2* xh2 = reinterpret_cast<const __half2*>(g_xh) + (size_t)b * HW * 32;

    // warp tile: 4 M-rows x 2 N-cols of 16x32
    const int mbase = (wid & 3) * 16;
    const int ncol  = wid >> 2;

    float acc[4][4];
    #pragma unroll
    for (int nt = 0; nt < 4; nt++)
        #pragma unroll
        for (int q = 0; q < 4; q++) acc[nt][q] = 0.0f;

    const int arow  = lane & 15;
    const int acolb = (lane >> 4) * 16;

    for (int ch = 0; ch < CHUNKS; ch++) {
        const int s = ch & 1;

        // ---- fill A[s]: warp = 8 pixels, lane = channel pair, fp16 HFMA2 interp ----
        {
            char* ah = smem + A_BUF(s);
            #pragma unroll
            for (int i = 0; i < 8; i++) {
                const int p = wid * 8 + i;
                const int4 id = sidx[p * KK + ch];
                const int4 wp = swgt[p * KK + ch];

                const __half2 v00 = __ldg(xh2 + (size_t)id.x * 32 + lane);
                const __half2 v01 = __ldg(xh2 + (size_t)id.y * 32 + lane);
                const __half2 v10 = __ldg(xh2 + (size_t)id.z * 32 + lane);
                const __half2 v11 = __ldg(xh2 + (size_t)id.w * 32 + lane);

                __half2 hv = __hmul2(v00, u2h2((uint32_t)wp.x));
                hv = __hfma2(v01, u2h2((uint32_t)wp.y), hv);
                hv = __hfma2(v10, u2h2((uint32_t)wp.z), hv);
                hv = __hfma2(v11, u2h2((uint32_t)wp.w), hv);

                const uint32_t sw = sw128((uint32_t)(p * 128 + lane * 4));
                *reinterpret_cast<uint32_t*>(ah + sw) = *reinterpret_cast<const uint32_t*>(&hv);
            }
        }
        __syncthreads();   // A[s] ready; also proves mma on this buffer (ch-2) is done

        // ---- warp MMAs: 4 k-steps x 4 n-tiles, single fp16 product ----
        const uint2* bfr = g_Bfrag + (size_t)(ch * KSTEPS) * 8 * 32;
        #pragma unroll
        for (int ks = 0; ks < KSTEPS; ks++) {
            uint32_t af[4];
            const uint32_t o0 = sw128((uint32_t)((mbase + arow) * 128 + ks * 32 + acolb));
            ldmatrix_x4(af[0], af[1], af[2], af[3], sbase + A_BUF(s) + o0);

            #pragma unroll
            for (int nt = 0; nt < 4; nt++) {
                const uint2 bf = __ldg(bfr + ((size_t)ks * 8 + (ncol * 4 + nt)) * 32 + lane);
                mma_f16(acc[nt][0], acc[nt][1], acc[nt][2], acc[nt][3],
                        af[0], af[1], af[2], af[3], bf.x, bf.y);
            }
        }
    }

    __syncthreads();   // ldmatrix reads done before epilogue overwrites smem

    // ---- epilogue: transpose through smem, coalesced stores ----
    float* s_out = reinterpret_cast<float*>(smem);   // [OO][SOUT_STRIDE]
    {
        const int g   = lane >> 2;
        const int tig = lane & 3;
        #pragma unroll
        for (int nt = 0; nt < 4; nt++) {
            const int o  = ncol * 32 + nt * 8 + 2 * tig;
            const int p0 = mbase + g;
            s_out[o * SOUT_STRIDE + p0]            = acc[nt][0];
            s_out[(o + 1) * SOUT_STRIDE + p0]      = acc[nt][1];
            s_out[o * SOUT_STRIDE + p0 + 8]        = acc[nt][2];
            s_out[(o + 1) * SOUT_STRIDE + p0 + 8]  = acc[nt][3];
        }
    }
    __syncthreads();

    {
        float* ob = out + (size_t)b * OO * NPX + px0;
        #pragma unroll
        for (int i = 0; i < MPX * OO / THREADS; i++) {
            const int idx = i * THREADS + t;
            const int p = idx & (MPX - 1);
            const int o = idx >> 6;
            ob[(size_t)o * NPX + p] = s_out[o * SOUT_STRIDE + p] + __ldg(bias + o);
        }
    }
}

extern "C" void kernel_launch(void* const* d_in, const int* in_sizes, int n_in,
                              void* d_out, int out_size) {
    const float* x      = (const float*)d_in[0];
    const float* offset = (const float*)d_in[1];
    const float* mask   = (const float*)d_in[2];
    const float* weight = (const float*)d_in[3];
    const float* bias   = (const float*)d_in[4];
    float* out = (float*)d_out;

    prep_kernel<<<TRANS_BLOCKS + WPREP_BLOCKS, 256>>>(x, weight);

    cudaFuncSetAttribute(dcn_kernel,
                         cudaFuncAttributeMaxDynamicSharedMemorySize, SMEM_TOTAL);

    dim3 grid(NPX / MPX, BB);   // (144, 4) = 576 blocks
    dcn_kernel<<<grid, THREADS, SMEM_TOTAL>>>(offset, mask, bias, out);
}

// round 15
// speedup vs baseline: 11.4744x; 1.1250x over previous
#include <cuda_runtime.h>
#include <cuda_fp16.h>
#include <cstdint>

// ModulatedDeformConv2d: B=4, C=64, H=W=96, O=64, 3x3, stride=1, pad=1, dil=1, DG=1.
#define BB 4
#define CC 64
#define HH 96
#define WW 96
#define OO 64
#define KK 9
#define HW (HH*WW)
#define NPX (96*96)         // 9216 output pixels per image
#define MPX 64              // pixels per block (GEMM M)
#define THREADS 256
#define CHUNKS 9
#define KSTEPS 4            // 64 / 16

// ---- shared memory ----
// A double buffer: fp16, 64 rows x 128B, SW128. buf s at s*8192.
#define A_BUF(s)   ((s) * 8192)
#define PIDX_OFF   16384                    // int4[576]  9216B (corner indices)
#define PWGT_OFF   (PIDX_OFF + 9216)        // int4[576]  9216B (4 x dup-half2 weights)
#define SMEM_TOTAL (PWGT_OFF + 9216)        // 34816
#define SOUT_STRIDE 68                      // epilogue [OO][68] floats (17408B, fits)

#define TRANS_BLOCKS (BB * HW / 96)         // 384
#define WPREP_BLOCKS 36

// NHWC fp16 copy of x: g_xh[b][hw][c]
__device__ __align__(16) __half g_xh[BB * HW * CC];
// Pre-packed fp16 B fragments, exact mma.sync lane order: {b0, b1} per lane.
__device__ __align__(16) uint2 g_Bfrag[CHUNKS * KSTEPS * 8 * 32];

__device__ __forceinline__ uint32_t smem_u32(const void* p) {
    uint32_t a;
    asm("{ .reg .u64 t; cvta.to.shared.u64 t, %1; cvt.u32.u64 %0, t; }" : "=r"(a) : "l"(p));
    return a;
}
__device__ __forceinline__ uint32_t sw128(uint32_t off) {
    return off ^ ((off >> 3) & 0x70);
}
__device__ __forceinline__ uint32_t dup_h2(float w) {
    const __half2 h = __half2half2(__float2half_rn(w));
    return *reinterpret_cast<const uint32_t*>(&h);
}
__device__ __forceinline__ __half2 u2h2(uint32_t u) {
    return *reinterpret_cast<const __half2*>(&u);
}
__device__ __forceinline__ uint32_t h2u(__half2 h) {
    return *reinterpret_cast<const uint32_t*>(&h);
}

__device__ __forceinline__ void ldmatrix_x4(uint32_t &r0, uint32_t &r1,
                                            uint32_t &r2, uint32_t &r3, uint32_t addr) {
    asm volatile("ldmatrix.sync.aligned.m8n8.x4.shared.b16 {%0,%1,%2,%3}, [%4];"
                 : "=r"(r0), "=r"(r1), "=r"(r2), "=r"(r3) : "r"(addr));
}

__device__ __forceinline__ void mma_f16(float &d0, float &d1, float &d2, float &d3,
                                        uint32_t a0, uint32_t a1, uint32_t a2, uint32_t a3,
                                        uint32_t b0, uint32_t b1) {
    asm volatile("mma.sync.aligned.m16n8k16.row.col.f32.f16.f16.f32 "
                 "{%0,%1,%2,%3}, {%4,%5,%6,%7}, {%8,%9}, {%0,%1,%2,%3};"
                 : "+f"(d0), "+f"(d1), "+f"(d2), "+f"(d3)
                 : "r"(a0), "r"(a1), "r"(a2), "r"(a3), "r"(b0), "r"(b1));
}

// ---- fused prep: NCHW->NHWC fp16 transpose (3 sub-tiles/block) + weight pack ----
__global__ void prep_kernel(const float* __restrict__ x,
                            const float* __restrict__ weight) {
    if (blockIdx.x < TRANS_BLOCKS) {
        __shared__ float tile[CC][33];
        const int t = threadIdx.x;
        #pragma unroll
        for (int sub = 0; sub < 3; sub++) {
            const int bhw0 = blockIdx.x * 96 + sub * 32;
            const int b    = bhw0 / HW;
            const int hwb  = bhw0 - b * HW;
            {
                const int tx = t & 31;
                const int c0 = t >> 5;
                #pragma unroll
                for (int j = 0; j < 8; j++) {
                    const int c = c0 + j * 8;
                    tile[c][tx] = x[((size_t)b * CC + c) * HW + hwb + tx];
                }
            }
            __syncthreads();
            {
                const int cp  = t & 31;
                const int hl0 = t >> 5;
                __half2* xh2 = reinterpret_cast<__half2*>(g_xh);
                #pragma unroll
                for (int j = 0; j < 4; j++) {
                    const int hl = hl0 + j * 8;
                    const float2 v = make_float2(tile[2 * cp][hl], tile[2 * cp + 1][hl]);
                    xh2[((size_t)b * HW + hwb + hl) * 32 + cp] = __float22half2_rn(v);
                }
            }
            __syncthreads();
        }
    } else {
        const int idx = (blockIdx.x - TRANS_BLOCKS) * blockDim.x + threadIdx.x;
        if (idx >= CHUNKS * KSTEPS * 8 * 32) return;
        const int lane  = idx & 31;
        const int ntile = (idx >> 5) & 7;
        const int kstep = (idx >> 8) & 3;
        const int chunk = idx >> 10;

        const int n  = ntile * 8 + (lane >> 2);
        const int c0 = kstep * 16 + 2 * (lane & 3);

        uint32_t hh[2];
        #pragma unroll
        for (int half = 0; half < 2; half++) {
            const int ca = c0 + half * 8;
            const float w0 = weight[n * (CC * KK) + ca * KK + chunk];
            const float w1 = weight[n * (CC * KK) + (ca + 1) * KK + chunk];
            const __half2 p = __float22half2_rn(make_float2(w0, w1));
            hh[half] = *reinterpret_cast<const uint32_t*>(&p);
        }
        g_Bfrag[idx] = make_uint2(hh[0], hh[1]);
    }
}

__global__ __launch_bounds__(THREADS, 4)
void dcn_kernel(const float* __restrict__ offset,
                const float* __restrict__ mask,
                const float* __restrict__ bias,
                float* __restrict__ out) {
    extern __shared__ char smem[];
    const uint32_t sbase = smem_u32(smem);

    const int t    = threadIdx.x;
    const int wid  = t >> 5;
    const int lane = t & 31;
    const int tile = blockIdx.x;     // 0..143
    const int b    = blockIdx.y;
    const int px0  = tile * MPX;

    // ---- phase 0: bilinear params for 64 px x 9 taps ----
    {
        int4* sidx = reinterpret_cast<int4*>(smem + PIDX_OFF);
        int4* swgt = reinterpret_cast<int4*>(smem + PWGT_OFF);
        const float* offb  = offset + (size_t)b * (2 * KK * NPX);
        const float* maskb = mask   + (size_t)b * (KK * NPX);
        for (int i = t; i < MPX * KK; i += THREADS) {
            const int p  = i / KK;
            const int k  = i - p * KK;
            const int pxg = px0 + p;
            const int ho = pxg / 96;
            const int wo = pxg - ho * 96;
            const int ky = k / 3;
            const int kx = k - ky * 3;

            const float off_y = __ldg(offb + (2 * k + 0) * NPX + pxg);
            const float off_x = __ldg(offb + (2 * k + 1) * NPX + pxg);
            const float m     = __ldg(maskb + k * NPX + pxg);

            const float py = (float)(ho - 1 + ky) + off_y;
            const float px = (float)(wo - 1 + kx) + off_x;

            const float y0f = floorf(py);
            const float x0f = floorf(px);
            const int y0 = (int)y0f, x0 = (int)x0f;
            const float ly = py - y0f, lx = px - x0f;
            const float hy = 1.0f - ly, hx = 1.0f - lx;
            const int y1 = y0 + 1, x1 = x0 + 1;

            const float vy0 = (y0 >= 0 && y0 < HH) ? 1.0f : 0.0f;
            const float vy1 = (y1 >= 0 && y1 < HH) ? 1.0f : 0.0f;
            const float vx0 = (x0 >= 0 && x0 < WW) ? 1.0f : 0.0f;
            const float vx1 = (x1 >= 0 && x1 < WW) ? 1.0f : 0.0f;

            const int cy0 = min(max(y0, 0), HH - 1);
            const int cy1 = min(max(y1, 0), HH - 1);
            const int cx0 = min(max(x0, 0), WW - 1);
            const int cx1 = min(max(x1, 0), WW - 1);

            int4 id;
            id.x = cy0 * WW + cx0;
            id.y = cy0 * WW + cx1;
            id.z = cy1 * WW + cx0;
            id.w = cy1 * WW + cx1;

            int4 wp;
            wp.x = (int)dup_h2(hy * hx * m * vy0 * vx0);
            wp.y = (int)dup_h2(hy * lx * m * vy0 * vx1);
            wp.z = (int)dup_h2(ly * hx * m * vy1 * vx0);
            wp.w = (int)dup_h2(ly * lx * m * vy1 * vx1);

            sidx[i] = id;
            swgt[i] = wp;
        }
    }
    __syncthreads();

    const int4* sidx = reinterpret_cast<const int4*>(smem + PIDX_OFF);
    const int4* swgt = reinterpret_cast<const int4*>(smem + PWGT_OFF);
    // uint2 view: spatial idx * 16 + channel-quad -> 4 fp16 channels
    const uint2* xh4 = reinterpret_cast<const uint2*>(g_xh) + (size_t)b * HW * 16;

    // warp tile: 4 M-rows x 2 N-cols of 16x32
    const int mbase = (wid & 3) * 16;
    const int ncol  = wid >> 2;

    // fill-role lane split: pp = pixel half, cq = channel quad
    const int pp = lane >> 4;
    const int cq = lane & 15;

    float acc[4][4];
    #pragma unroll
    for (int nt = 0; nt < 4; nt++)
        #pragma unroll
        for (int q = 0; q < 4; q++) acc[nt][q] = 0.0f;

    const int arow  = lane & 15;
    const int acolb = (lane >> 4) * 16;

    for (int ch = 0; ch < CHUNKS; ch++) {
        const int s = ch & 1;

        // ---- fill A[s]: warp = 8 pixels, 2 px per iteration (lane = pp,cq) ----
        {
            char* ah = smem + A_BUF(s);
            #pragma unroll
            for (int i = 0; i < 4; i++) {
                const int p = wid * 8 + i * 2 + pp;
                const int4 id = sidx[p * KK + ch];
                const int4 wp = swgt[p * KK + ch];

                const uint2 v00 = __ldg(xh4 + (size_t)id.x * 16 + cq);
                const uint2 v01 = __ldg(xh4 + (size_t)id.y * 16 + cq);
                const uint2 v10 = __ldg(xh4 + (size_t)id.z * 16 + cq);
                const uint2 v11 = __ldg(xh4 + (size_t)id.w * 16 + cq);

                const __half2 w00 = u2h2((uint32_t)wp.x);
                const __half2 w01 = u2h2((uint32_t)wp.y);
                const __half2 w10 = u2h2((uint32_t)wp.z);
                const __half2 w11 = u2h2((uint32_t)wp.w);

                __half2 h0 = __hmul2(u2h2(v00.x), w00);
                __half2 h1 = __hmul2(u2h2(v00.y), w00);
                h0 = __hfma2(u2h2(v01.x), w01, h0);
                h1 = __hfma2(u2h2(v01.y), w01, h1);
                h0 = __hfma2(u2h2(v10.x), w10, h0);
                h1 = __hfma2(u2h2(v10.y), w10, h1);
                h0 = __hfma2(u2h2(v11.x), w11, h0);
                h1 = __hfma2(u2h2(v11.y), w11, h1);

                const uint32_t sw = sw128((uint32_t)(p * 128 + cq * 8));
                *reinterpret_cast<uint2*>(ah + sw) = make_uint2(h2u(h0), h2u(h1));
            }
        }

        // ---- prefetch ks=0 B fragments (gmem-only; overlaps barrier wait) ----
        const uint2* bfr = g_Bfrag + (size_t)(ch * KSTEPS) * 8 * 32;
        uint2 bf0[4];
        #pragma unroll
        for (int nt = 0; nt < 4; nt++)
            bf0[nt] = __ldg(bfr + ((size_t)(ncol * 4 + nt)) * 32 + lane);

        __syncthreads();   // A[s] ready; also proves mma on this buffer (ch-2) is done

        // ---- warp MMAs: 4 k-steps x 4 n-tiles ----
        #pragma unroll
        for (int ks = 0; ks < KSTEPS; ks++) {
            uint32_t af[4];
            const uint32_t o0 = sw128((uint32_t)((mbase + arow) * 128 + ks * 32 + acolb));
            ldmatrix_x4(af[0], af[1], af[2], af[3], sbase + A_BUF(s) + o0);

            #pragma unroll
            for (int nt = 0; nt < 4; nt++) {
                const uint2 bf = (ks == 0) ? bf0[nt]
                    : __ldg(bfr + ((size_t)ks * 8 + (ncol * 4 + nt)) * 32 + lane);
                mma_f16(acc[nt][0], acc[nt][1], acc[nt][2], acc[nt][3],
                        af[0], af[1], af[2], af[3], bf.x, bf.y);
            }
        }
    }

    __syncthreads();   // ldmatrix reads done before epilogue overwrites smem

    // ---- epilogue: transpose through smem, coalesced stores ----
    float* s_out = reinterpret_cast<float*>(smem);   // [OO][SOUT_STRIDE]
    {
        const int g   = lane >> 2;
        const int tig = lane & 3;
        #pragma unroll
        for (int nt = 0; nt < 4; nt++) {
            const int o  = ncol * 32 + nt * 8 + 2 * tig;
            const int p0 = mbase + g;
            s_out[o * SOUT_STRIDE + p0]            = acc[nt][0];
            s_out[(o + 1) * SOUT_STRIDE + p0]      = acc[nt][1];
            s_out[o * SOUT_STRIDE + p0 + 8]        = acc[nt][2];
            s_out[(o + 1) * SOUT_STRIDE + p0 + 8]  = acc[nt][3];
        }
    }
    __syncthreads();

    {
        float* ob = out + (size_t)b * OO * NPX + px0;
        #pragma unroll
        for (int i = 0; i < MPX * OO / THREADS; i++) {
            const int idx = i * THREADS + t;
            const int p = idx & (MPX - 1);
            const int o = idx >> 6;
            ob[(size_t)o * NPX + p] = s_out[o * SOUT_STRIDE + p] + __ldg(bias + o);
        }
    }
}

extern "C" void kernel_launch(void* const* d_in, const int* in_sizes, int n_in,
                              void* d_out, int out_size) {
    const float* x      = (const float*)d_in[0];
    const float* offset = (const float*)d_in[1];
    const float* mask   = (const float*)d_in[2];
    const float* weight = (const float*)d_in[3];
    const float* bias   = (const float*)d_in[4];
    float* out = (float*)d_out;

    prep_kernel<<<TRANS_BLOCKS + WPREP_BLOCKS, 256>>>(x, weight);

    cudaFuncSetAttribute(dcn_kernel,
                         cudaFuncAttributeMaxDynamicSharedMemorySize, SMEM_TOTAL);

    dim3 grid(NPX / MPX, BB);   // (144, 4) = 576 blocks
    dcn_kernel<<<grid, THREADS, SMEM_TOTAL>>>(offset, mask, bias, out);
}

// round 16
// speedup vs baseline: 11.8759x; 1.0350x over previous
#include <cuda_runtime.h>
#include <cuda_fp16.h>
#include <cstdint>

// ModulatedDeformConv2d: B=4, C=64, H=W=96, O=64, 3x3, stride=1, pad=1, dil=1, DG=1.
#define BB 4
#define CC 64
#define HH 96
#define WW 96
#define OO 64
#define KK 9
#define HW (HH*WW)
#define NPX (96*96)         // 9216 output pixels per image
#define MPX 64              // pixels per block (GEMM M)
#define THREADS 256
#define CHUNKS 9
#define KSTEPS 4            // 64 / 16

// ---- shared memory ----
// A double buffer: fp16, 64 rows x 128B, SW128. buf s at s*8192.
#define A_BUF(s)   ((s) * 8192)
#define PIDX_OFF   16384                    // int4[576]  9216B (corner indices)
#define PWGT_OFF   (PIDX_OFF + 9216)        // int4[576]  9216B (4 x dup-half2 weights)
#define SMEM_TOTAL (PWGT_OFF + 9216)        // 34816
#define SOUT_STRIDE 68                      // epilogue [OO][68] floats (17408B, fits)

#define TRANS_BLOCKS (BB * HW / 96)         // 384
#define WPREP_BLOCKS 36

// NHWC fp16 copy of x: g_xh[b][hw][c]
__device__ __align__(16) __half g_xh[BB * HW * CC];
// Pre-packed fp16 B fragments, ks-paired: {b0(ks even), b1(ks even), b0(ks odd), b1(ks odd)}
// index: ((chunk*2 + ks2)*8 + ntile)*32 + lane
__device__ __align__(16) uint4 g_Bfrag4[CHUNKS * 2 * 8 * 32];

__device__ __forceinline__ uint32_t smem_u32(const void* p) {
    uint32_t a;
    asm("{ .reg .u64 t; cvta.to.shared.u64 t, %1; cvt.u32.u64 %0, t; }" : "=r"(a) : "l"(p));
    return a;
}
__device__ __forceinline__ uint32_t sw128(uint32_t off) {
    return off ^ ((off >> 3) & 0x70);
}
__device__ __forceinline__ uint32_t dup_h2(float w) {
    const __half2 h = __half2half2(__float2half_rn(w));
    return *reinterpret_cast<const uint32_t*>(&h);
}
__device__ __forceinline__ __half2 u2h2(uint32_t u) {
    return *reinterpret_cast<const __half2*>(&u);
}
__device__ __forceinline__ uint32_t h2u(__half2 h) {
    return *reinterpret_cast<const uint32_t*>(&h);
}

__device__ __forceinline__ void ldmatrix_x4(uint32_t &r0, uint32_t &r1,
                                            uint32_t &r2, uint32_t &r3, uint32_t addr) {
    asm volatile("ldmatrix.sync.aligned.m8n8.x4.shared.b16 {%0,%1,%2,%3}, [%4];"
                 : "=r"(r0), "=r"(r1), "=r"(r2), "=r"(r3) : "r"(addr));
}

__device__ __forceinline__ void mma_f16(float &d0, float &d1, float &d2, float &d3,
                                        uint32_t a0, uint32_t a1, uint32_t a2, uint32_t a3,
                                        uint32_t b0, uint32_t b1) {
    asm volatile("mma.sync.aligned.m16n8k16.row.col.f32.f16.f16.f32 "
                 "{%0,%1,%2,%3}, {%4,%5,%6,%7}, {%8,%9}, {%0,%1,%2,%3};"
                 : "+f"(d0), "+f"(d1), "+f"(d2), "+f"(d3)
                 : "r"(a0), "r"(a1), "r"(a2), "r"(a3), "r"(b0), "r"(b1));
}

// ---- fused prep: NCHW->NHWC fp16 transpose (3 sub-tiles/block) + weight pack ----
__global__ void prep_kernel(const float* __restrict__ x,
                            const float* __restrict__ weight) {
    if (blockIdx.x < TRANS_BLOCKS) {
        __shared__ float tile[CC][33];
        const int t = threadIdx.x;
        #pragma unroll
        for (int sub = 0; sub < 3; sub++) {
            const int bhw0 = blockIdx.x * 96 + sub * 32;
            const int b    = bhw0 / HW;
            const int hwb  = bhw0 - b * HW;
            {
                const int tx = t & 31;
                const int c0 = t >> 5;
                #pragma unroll
                for (int j = 0; j < 8; j++) {
                    const int c = c0 + j * 8;
                    tile[c][tx] = x[((size_t)b * CC + c) * HW + hwb + tx];
                }
            }
            __syncthreads();
            {
                const int cp  = t & 31;
                const int hl0 = t >> 5;
                __half2* xh2 = reinterpret_cast<__half2*>(g_xh);
                #pragma unroll
                for (int j = 0; j < 4; j++) {
                    const int hl = hl0 + j * 8;
                    const float2 v = make_float2(tile[2 * cp][hl], tile[2 * cp + 1][hl]);
                    xh2[((size_t)b * HW + hwb + hl) * 32 + cp] = __float22half2_rn(v);
                }
            }
            __syncthreads();
        }
    } else {
        // one thread packs one (chunk, ks2, ntile, lane) uint4 (both ks of the pair)
        const int idx = (blockIdx.x - TRANS_BLOCKS) * blockDim.x + threadIdx.x;
        if (idx >= CHUNKS * 2 * 8 * 32) return;
        const int lane  = idx & 31;
        const int ntile = (idx >> 5) & 7;
        const int ks2   = (idx >> 8) & 1;
        const int chunk = idx >> 9;

        const int n = ntile * 8 + (lane >> 2);

        uint32_t f[4];
        #pragma unroll
        for (int kodd = 0; kodd < 2; kodd++) {
            const int kstep = ks2 * 2 + kodd;
            const int c0 = kstep * 16 + 2 * (lane & 3);
            #pragma unroll
            for (int half = 0; half < 2; half++) {
                const int ca = c0 + half * 8;
                const float w0 = weight[n * (CC * KK) + ca * KK + chunk];
                const float w1 = weight[n * (CC * KK) + (ca + 1) * KK + chunk];
                const __half2 p = __float22half2_rn(make_float2(w0, w1));
                f[kodd * 2 + half] = *reinterpret_cast<const uint32_t*>(&p);
            }
        }
        g_Bfrag4[idx] = make_uint4(f[0], f[1], f[2], f[3]);
    }
}

__global__ __launch_bounds__(THREADS, 4)
void dcn_kernel(const float* __restrict__ offset,
                const float* __restrict__ mask,
                const float* __restrict__ bias,
                float* __restrict__ out) {
    extern __shared__ char smem[];
    const uint32_t sbase = smem_u32(smem);

    const int t    = threadIdx.x;
    const int wid  = t >> 5;
    const int lane = t & 31;
    const int tile = blockIdx.x;     // 0..143
    const int b    = blockIdx.y;
    const int px0  = tile * MPX;

    // ---- phase 0: bilinear params for 64 px x 9 taps ----
    {
        int4* sidx = reinterpret_cast<int4*>(smem + PIDX_OFF);
        int4* swgt = reinterpret_cast<int4*>(smem + PWGT_OFF);
        const float* offb  = offset + (size_t)b * (2 * KK * NPX);
        const float* maskb = mask   + (size_t)b * (KK * NPX);
        for (int i = t; i < MPX * KK; i += THREADS) {
            const int p  = i / KK;
            const int k  = i - p * KK;
            const int pxg = px0 + p;
            const int ho = pxg / 96;
            const int wo = pxg - ho * 96;
            const int ky = k / 3;
            const int kx = k - ky * 3;

            const float off_y = __ldg(offb + (2 * k + 0) * NPX + pxg);
            const float off_x = __ldg(offb + (2 * k + 1) * NPX + pxg);
            const float m     = __ldg(maskb + k * NPX + pxg);

            const float py = (float)(ho - 1 + ky) + off_y;
            const float px = (float)(wo - 1 + kx) + off_x;

            const float y0f = floorf(py);
            const float x0f = floorf(px);
            const int y0 = (int)y0f, x0 = (int)x0f;
            const float ly = py - y0f, lx = px - x0f;
            const float hy = 1.0f - ly, hx = 1.0f - lx;
            const int y1 = y0 + 1, x1 = x0 + 1;

            const float vy0 = (y0 >= 0 && y0 < HH) ? 1.0f : 0.0f;
            const float vy1 = (y1 >= 0 && y1 < HH) ? 1.0f : 0.0f;
            const float vx0 = (x0 >= 0 && x0 < WW) ? 1.0f : 0.0f;
            const float vx1 = (x1 >= 0 && x1 < WW) ? 1.0f : 0.0f;

            const int cy0 = min(max(y0, 0), HH - 1);
            const int cy1 = min(max(y1, 0), HH - 1);
            const int cx0 = min(max(x0, 0), WW - 1);
            const int cx1 = min(max(x1, 0), WW - 1);

            int4 id;
            id.x = cy0 * WW + cx0;
            id.y = cy0 * WW + cx1;
            id.z = cy1 * WW + cx0;
            id.w = cy1 * WW + cx1;

            int4 wp;
            wp.x = (int)dup_h2(hy * hx * m * vy0 * vx0);
            wp.y = (int)dup_h2(hy * lx * m * vy0 * vx1);
            wp.z = (int)dup_h2(ly * hx * m * vy1 * vx0);
            wp.w = (int)dup_h2(ly * lx * m * vy1 * vx1);

            sidx[i] = id;
            swgt[i] = wp;
        }
    }
    __syncthreads();

    const int4* sidx = reinterpret_cast<const int4*>(smem + PIDX_OFF);
    const int4* swgt = reinterpret_cast<const int4*>(smem + PWGT_OFF);
    // uint4 view: spatial idx * 8 + channel-oct -> 8 fp16 channels (16B)
    const uint4* xh8 = reinterpret_cast<const uint4*>(g_xh) + (size_t)b * HW * 8;

    // warp tile: 4 M-rows x 2 N-cols of 16x32
    const int mbase = (wid & 3) * 16;
    const int ncol  = wid >> 2;

    // fill-role lane split: pq = pixel quad, co = channel oct
    const int pq = lane >> 3;     // 0..3
    const int co = lane & 7;      // 0..7

    float acc[4][4];
    #pragma unroll
    for (int nt = 0; nt < 4; nt++)
        #pragma unroll
        for (int q = 0; q < 4; q++) acc[nt][q] = 0.0f;

    const int arow  = lane & 15;
    const int acolb = (lane >> 4) * 16;

    for (int ch = 0; ch < CHUNKS; ch++) {
        const int s = ch & 1;

        // ---- fill A[s]: warp = 8 pixels, 4 px per iteration (lane = pq,co) ----
        {
            char* ah = smem + A_BUF(s);
            #pragma unroll
            for (int i = 0; i < 2; i++) {
                const int p = wid * 8 + i * 4 + pq;
                const int4 id = sidx[p * KK + ch];
                const int4 wp = swgt[p * KK + ch];

                const uint4 v00 = __ldg(xh8 + (size_t)id.x * 8 + co);
                const uint4 v01 = __ldg(xh8 + (size_t)id.y * 8 + co);
                const uint4 v10 = __ldg(xh8 + (size_t)id.z * 8 + co);
                const uint4 v11 = __ldg(xh8 + (size_t)id.w * 8 + co);

                const __half2 w00 = u2h2((uint32_t)wp.x);
                const __half2 w01 = u2h2((uint32_t)wp.y);
                const __half2 w10 = u2h2((uint32_t)wp.z);
                const __half2 w11 = u2h2((uint32_t)wp.w);

                __half2 h0 = __hmul2(u2h2(v00.x), w00);
                __half2 h1 = __hmul2(u2h2(v00.y), w00);
                __half2 h2 = __hmul2(u2h2(v00.z), w00);
                __half2 h3 = __hmul2(u2h2(v00.w), w00);
                h0 = __hfma2(u2h2(v01.x), w01, h0);
                h1 = __hfma2(u2h2(v01.y), w01, h1);
                h2 = __hfma2(u2h2(v01.z), w01, h2);
                h3 = __hfma2(u2h2(v01.w), w01, h3);
                h0 = __hfma2(u2h2(v10.x), w10, h0);
                h1 = __hfma2(u2h2(v10.y), w10, h1);
                h2 = __hfma2(u2h2(v10.z), w10, h2);
                h3 = __hfma2(u2h2(v10.w), w10, h3);
                h0 = __hfma2(u2h2(v11.x), w11, h0);
                h1 = __hfma2(u2h2(v11.y), w11, h1);
                h2 = __hfma2(u2h2(v11.z), w11, h2);
                h3 = __hfma2(u2h2(v11.w), w11, h3);

                const uint32_t sw = sw128((uint32_t)(p * 128 + co * 16));
                *reinterpret_cast<uint4*>(ah + sw) =
                    make_uint4(h2u(h0), h2u(h1), h2u(h2), h2u(h3));
            }
        }

        // ---- prefetch ks2=0 B fragments (gmem-only; overlaps barrier wait) ----
        const uint4* bfr = g_Bfrag4 + (size_t)(ch * 2) * 8 * 32;
        uint4 bf0[4];
        #pragma unroll
        for (int nt = 0; nt < 4; nt++)
            bf0[nt] = __ldg(bfr + ((size_t)(ncol * 4 + nt)) * 32 + lane);

        __syncthreads();   // A[s] ready; also proves mma on this buffer (ch-2) is done

        // ---- warp MMAs: 2 ks-pairs x 4 n-tiles x 2 MMAs ----
        #pragma unroll
        for (int ks2 = 0; ks2 < 2; ks2++) {
            uint32_t a0[4], a1[4];
            const uint32_t oa = sw128((uint32_t)((mbase + arow) * 128 + ks2 * 64 + acolb));
            const uint32_t ob = sw128((uint32_t)((mbase + arow) * 128 + ks2 * 64 + 32 + acolb));
            ldmatrix_x4(a0[0], a0[1], a0[2], a0[3], sbase + A_BUF(s) + oa);
            ldmatrix_x4(a1[0], a1[1], a1[2], a1[3], sbase + A_BUF(s) + ob);

            #pragma unroll
            for (int nt = 0; nt < 4; nt++) {
                const uint4 bf = (ks2 == 0) ? bf0[nt]
                    : __ldg(bfr + ((size_t)8 + (ncol * 4 + nt)) * 32 + lane);
                mma_f16(acc[nt][0], acc[nt][1], acc[nt][2], acc[nt][3],
                        a0[0], a0[1], a0[2], a0[3], bf.x, bf.y);
                mma_f16(acc[nt][0], acc[nt][1], acc[nt][2], acc[nt][3],
                        a1[0], a1[1], a1[2], a1[3], bf.z, bf.w);
            }
        }
    }

    __syncthreads();   // ldmatrix reads done before epilogue overwrites smem

    // ---- epilogue: transpose through smem, coalesced stores ----
    float* s_out = reinterpret_cast<float*>(smem);   // [OO][SOUT_STRIDE]
    {
        const int g   = lane >> 2;
        const int tig = lane & 3;
        #pragma unroll
        for (int nt = 0; nt < 4; nt++) {
            const int o  = ncol * 32 + nt * 8 + 2 * tig;
            const int p0 = mbase + g;
            s_out[o * SOUT_STRIDE + p0]            = acc[nt][0];
            s_out[(o + 1) * SOUT_STRIDE + p0]      = acc[nt][1];
            s_out[o * SOUT_STRIDE + p0 + 8]        = acc[nt][2];
            s_out[(o + 1) * SOUT_STRIDE + p0 + 8]  = acc[nt][3];
        }
    }
    __syncthreads();

    {
        float* ob = out + (size_t)b * OO * NPX + px0;
        #pragma unroll
        for (int i = 0; i < MPX * OO / THREADS; i++) {
            const int idx = i * THREADS + t;
            const int p = idx & (MPX - 1);
            const int o = idx >> 6;
            ob[(size_t)o * NPX + p] = s_out[o * SOUT_STRIDE + p] + __ldg(bias + o);
        }
    }
}

extern "C" void kernel_launch(void* const* d_in, const int* in_sizes, int n_in,
                              void* d_out, int out_size) {
    const float* x      = (const float*)d_in[0];
    const float* offset = (const float*)d_in[1];
    const float* mask   = (const float*)d_in[2];
    const float* weight = (const float*)d_in[3];
    const float* bias   = (const float*)d_in[4];
    float* out = (float*)d_out;

    prep_kernel<<<TRANS_BLOCKS + WPREP_BLOCKS, 256>>>(x, weight);

    cudaFuncSetAttribute(dcn_kernel,
                         cudaFuncAttributeMaxDynamicSharedMemorySize, SMEM_TOTAL);

    dim3 grid(NPX / MPX, BB);   // (144, 4) = 576 blocks
    dcn_kernel<<<grid, THREADS, SMEM_TOTAL>>>(offset, mask, bias, out);
}

// round 17
// speedup vs baseline: 12.2931x; 1.0351x over previous
#include <cuda_runtime.h>
#include <cuda_fp16.h>
#include <cstdint>

// ModulatedDeformConv2d: B=4, C=64, H=W=96, O=64, 3x3, stride=1, pad=1, dil=1, DG=1.
#define BB 4
#define CC 64
#define HH 96
#define WW 96
#define OO 64
#define KK 9
#define HW (HH*WW)
#define NPX (96*96)         // 9216 output pixels per image
#define MPX 32              // pixels per block (GEMM M)
#define THREADS 128
#define CHUNKS 9

// ---- shared memory ----
// A double buffer: fp16, 32 rows x 128B, SW128. buf s at s*4096.
#define A_BUF(s)   ((s) * 4096)
#define PIDX_OFF   8192                     // int4[288]  4608B (corner indices)
#define PWGT_OFF   (PIDX_OFF + 4608)        // int4[288]  4608B (4 x dup-half2 weights)
#define SMEM_TOTAL (PWGT_OFF + 4608)        // 17408
#define SOUT_STRIDE 36                      // epilogue [OO][36] floats = 9216B (fits)

#define TRANS_BLOCKS (BB * HW / 96)         // 384
#define WPREP_BLOCKS 36

// NHWC fp16 copy of x: g_xh[b][hw][c]
__device__ __align__(16) __half g_xh[BB * HW * CC];
// Pre-packed fp16 B fragments, ks-paired: {b0(ks even), b1(ks even), b0(ks odd), b1(ks odd)}
// index: ((chunk*2 + ks2)*8 + ntile)*32 + lane
__device__ __align__(16) uint4 g_Bfrag4[CHUNKS * 2 * 8 * 32];

__device__ __forceinline__ uint32_t smem_u32(const void* p) {
    uint32_t a;
    asm("{ .reg .u64 t; cvta.to.shared.u64 t, %1; cvt.u32.u64 %0, t; }" : "=r"(a) : "l"(p));
    return a;
}
__device__ __forceinline__ uint32_t sw128(uint32_t off) {
    return off ^ ((off >> 3) & 0x70);
}
__device__ __forceinline__ uint32_t dup_h2(float w) {
    const __half2 h = __half2half2(__float2half_rn(w));
    return *reinterpret_cast<const uint32_t*>(&h);
}
__device__ __forceinline__ __half2 u2h2(uint32_t u) {
    return *reinterpret_cast<const __half2*>(&u);
}
__device__ __forceinline__ uint32_t h2u(__half2 h) {
    return *reinterpret_cast<const uint32_t*>(&h);
}

__device__ __forceinline__ void ldmatrix_x4(uint32_t &r0, uint32_t &r1,
                                            uint32_t &r2, uint32_t &r3, uint32_t addr) {
    asm volatile("ldmatrix.sync.aligned.m8n8.x4.shared.b16 {%0,%1,%2,%3}, [%4];"
                 : "=r"(r0), "=r"(r1), "=r"(r2), "=r"(r3) : "r"(addr));
}

__device__ __forceinline__ void mma_f16(float &d0, float &d1, float &d2, float &d3,
                                        uint32_t a0, uint32_t a1, uint32_t a2, uint32_t a3,
                                        uint32_t b0, uint32_t b1) {
    asm volatile("mma.sync.aligned.m16n8k16.row.col.f32.f16.f16.f32 "
                 "{%0,%1,%2,%3}, {%4,%5,%6,%7}, {%8,%9}, {%0,%1,%2,%3};"
                 : "+f"(d0), "+f"(d1), "+f"(d2), "+f"(d3)
                 : "r"(a0), "r"(a1), "r"(a2), "r"(a3), "r"(b0), "r"(b1));
}

// ---- fused prep: NCHW->NHWC fp16 transpose (3 sub-tiles/block) + weight pack ----
__global__ void prep_kernel(const float* __restrict__ x,
                            const float* __restrict__ weight) {
    if (blockIdx.x < TRANS_BLOCKS) {
        __shared__ float tile[CC][33];
        const int t = threadIdx.x;
        #pragma unroll
        for (int sub = 0; sub < 3; sub++) {
            const int bhw0 = blockIdx.x * 96 + sub * 32;
            const int b    = bhw0 / HW;
            const int hwb  = bhw0 - b * HW;
            {
                const int tx = t & 31;
                const int c0 = t >> 5;
                #pragma unroll
                for (int j = 0; j < 8; j++) {
                    const int c = c0 + j * 8;
                    tile[c][tx] = x[((size_t)b * CC + c) * HW + hwb + tx];
                }
            }
            __syncthreads();
            {
                const int cp  = t & 31;
                const int hl0 = t >> 5;
                __half2* xh2 = reinterpret_cast<__half2*>(g_xh);
                #pragma unroll
                for (int j = 0; j < 4; j++) {
                    const int hl = hl0 + j * 8;
                    const float2 v = make_float2(tile[2 * cp][hl], tile[2 * cp + 1][hl]);
                    xh2[((size_t)b * HW + hwb + hl) * 32 + cp] = __float22half2_rn(v);
                }
            }
            __syncthreads();
        }
    } else {
        const int idx = (blockIdx.x - TRANS_BLOCKS) * blockDim.x + threadIdx.x;
        if (idx >= CHUNKS * 2 * 8 * 32) return;
        const int lane  = idx & 31;
        const int ntile = (idx >> 5) & 7;
        const int ks2   = (idx >> 8) & 1;
        const int chunk = idx >> 9;

        const int n = ntile * 8 + (lane >> 2);

        uint32_t f[4];
        #pragma unroll
        for (int kodd = 0; kodd < 2; kodd++) {
            const int kstep = ks2 * 2 + kodd;
            const int c0 = kstep * 16 + 2 * (lane & 3);
            #pragma unroll
            for (int half = 0; half < 2; half++) {
                const int ca = c0 + half * 8;
                const float w0 = weight[n * (CC * KK) + ca * KK + chunk];
                const float w1 = weight[n * (CC * KK) + (ca + 1) * KK + chunk];
                const __half2 p = __float22half2_rn(make_float2(w0, w1));
                f[kodd * 2 + half] = *reinterpret_cast<const uint32_t*>(&p);
            }
        }
        g_Bfrag4[idx] = make_uint4(f[0], f[1], f[2], f[3]);
    }
}

__global__ __launch_bounds__(THREADS, 8)
void dcn_kernel(const float* __restrict__ offset,
                const float* __restrict__ mask,
                const float* __restrict__ bias,
                float* __restrict__ out) {
    extern __shared__ char smem[];
    const uint32_t sbase = smem_u32(smem);

    const int t    = threadIdx.x;
    const int wid  = t >> 5;        // 0..3
    const int lane = t & 31;
    const int tile = blockIdx.x;    // 0..287
    const int b    = blockIdx.y;
    const int px0  = tile * MPX;

    // ---- phase 0: bilinear params for 32 px x 9 taps (overlaps prep via PDL) ----
    {
        int4* sidx = reinterpret_cast<int4*>(smem + PIDX_OFF);
        int4* swgt = reinterpret_cast<int4*>(smem + PWGT_OFF);
        const float* offb  = offset + (size_t)b * (2 * KK * NPX);
        const float* maskb = mask   + (size_t)b * (KK * NPX);
        for (int i = t; i < MPX * KK; i += THREADS) {
            const int p  = i / KK;
            const int k  = i - p * KK;
            const int pxg = px0 + p;
            const int ho = pxg / 96;
            const int wo = pxg - ho * 96;
            const int ky = k / 3;
            const int kx = k - ky * 3;

            const float off_y = __ldg(offb + (2 * k + 0) * NPX + pxg);
            const float off_x = __ldg(offb + (2 * k + 1) * NPX + pxg);
            const float m     = __ldg(maskb + k * NPX + pxg);

            const float py = (float)(ho - 1 + ky) + off_y;
            const float px = (float)(wo - 1 + kx) + off_x;

            const float y0f = floorf(py);
            const float x0f = floorf(px);
            const int y0 = (int)y0f, x0 = (int)x0f;
            const float ly = py - y0f, lx = px - x0f;
            const float hy = 1.0f - ly, hx = 1.0f - lx;
            const int y1 = y0 + 1, x1 = x0 + 1;

            const float vy0 = (y0 >= 0 && y0 < HH) ? 1.0f : 0.0f;
            const float vy1 = (y1 >= 0 && y1 < HH) ? 1.0f : 0.0f;
            const float vx0 = (x0 >= 0 && x0 < WW) ? 1.0f : 0.0f;
            const float vx1 = (x1 >= 0 && x1 < WW) ? 1.0f : 0.0f;

            const int cy0 = min(max(y0, 0), HH - 1);
            const int cy1 = min(max(y1, 0), HH - 1);
            const int cx0 = min(max(x0, 0), WW - 1);
            const int cx1 = min(max(x1, 0), WW - 1);

            int4 id;
            id.x = cy0 * WW + cx0;
            id.y = cy0 * WW + cx1;
            id.z = cy1 * WW + cx0;
            id.w = cy1 * WW + cx1;

            int4 wp;
            wp.x = (int)dup_h2(hy * hx * m * vy0 * vx0);
            wp.y = (int)dup_h2(hy * lx * m * vy0 * vx1);
            wp.z = (int)dup_h2(ly * hx * m * vy1 * vx0);
            wp.w = (int)dup_h2(ly * lx * m * vy1 * vx1);

            sidx[i] = id;
            swgt[i] = wp;
        }
    }
    __syncthreads();

    // Wait for prep_kernel (PDL): everything below reads g_xh / g_Bfrag4.
    cudaGridDependencySynchronize();

    const int4* sidx = reinterpret_cast<const int4*>(smem + PIDX_OFF);
    const int4* swgt = reinterpret_cast<const int4*>(smem + PWGT_OFF);
    // uint4 view: spatial idx * 8 + channel-oct -> 8 fp16 channels (16B)
    const uint4* xh8 = reinterpret_cast<const uint4*>(g_xh) + (size_t)b * HW * 8;

    // warp tile: 2 M-rows x 2 N-cols of 16x32
    const int mbase = (wid & 1) * 16;
    const int ncol  = wid >> 1;

    // fill-role lane split: pq = pixel quad, co = channel oct
    const int pq = lane >> 3;     // 0..3
    const int co = lane & 7;      // 0..7

    float acc[4][4];
    #pragma unroll
    for (int nt = 0; nt < 4; nt++)
        #pragma unroll
        for (int q = 0; q < 4; q++) acc[nt][q] = 0.0f;

    const int arow  = lane & 15;
    const int acolb = (lane >> 4) * 16;

    for (int ch = 0; ch < CHUNKS; ch++) {
        const int s = ch & 1;

        // ---- fill A[s]: warp = 8 pixels, 4 px per iteration (lane = pq,co) ----
        {
            char* ah = smem + A_BUF(s);
            #pragma unroll
            for (int i = 0; i < 2; i++) {
                const int p = wid * 8 + i * 4 + pq;
                const int4 id = sidx[p * KK + ch];
                const int4 wp = swgt[p * KK + ch];

                const uint4 v00 = __ldg(xh8 + (size_t)id.x * 8 + co);
                const uint4 v01 = __ldg(xh8 + (size_t)id.y * 8 + co);
                const uint4 v10 = __ldg(xh8 + (size_t)id.z * 8 + co);
                const uint4 v11 = __ldg(xh8 + (size_t)id.w * 8 + co);

                const __half2 w00 = u2h2((uint32_t)wp.x);
                const __half2 w01 = u2h2((uint32_t)wp.y);
                const __half2 w10 = u2h2((uint32_t)wp.z);
                const __half2 w11 = u2h2((uint32_t)wp.w);

                __half2 h0 = __hmul2(u2h2(v00.x), w00);
                __half2 h1 = __hmul2(u2h2(v00.y), w00);
                __half2 h2 = __hmul2(u2h2(v00.z), w00);
                __half2 h3 = __hmul2(u2h2(v00.w), w00);
                h0 = __hfma2(u2h2(v01.x), w01, h0);
                h1 = __hfma2(u2h2(v01.y), w01, h1);
                h2 = __hfma2(u2h2(v01.z), w01, h2);
                h3 = __hfma2(u2h2(v01.w), w01, h3);
                h0 = __hfma2(u2h2(v10.x), w10, h0);
                h1 = __hfma2(u2h2(v10.y), w10, h1);
                h2 = __hfma2(u2h2(v10.z), w10, h2);
                h3 = __hfma2(u2h2(v10.w), w10, h3);
                h0 = __hfma2(u2h2(v11.x), w11, h0);
                h1 = __hfma2(u2h2(v11.y), w11, h1);
                h2 = __hfma2(u2h2(v11.z), w11, h2);
                h3 = __hfma2(u2h2(v11.w), w11, h3);

                const uint32_t sw = sw128((uint32_t)(p * 128 + co * 16));
                *reinterpret_cast<uint4*>(ah + sw) =
                    make_uint4(h2u(h0), h2u(h1), h2u(h2), h2u(h3));
            }
        }

        // ---- prefetch ks2=0 B fragments (gmem-only; overlaps barrier wait) ----
        const uint4* bfr = g_Bfrag4 + (size_t)(ch * 2) * 8 * 32;
        uint4 bf0[4];
        #pragma unroll
        for (int nt = 0; nt < 4; nt++)
            bf0[nt] = __ldg(bfr + ((size_t)(ncol * 4 + nt)) * 32 + lane);

        __syncthreads();   // A[s] ready; also proves mma on this buffer (ch-2) is done

        // ---- warp MMAs: 2 ks-pairs x 4 n-tiles x 2 MMAs ----
        #pragma unroll
        for (int ks2 = 0; ks2 < 2; ks2++) {
            uint32_t a0[4], a1[4];
            const uint32_t oa = sw128((uint32_t)((mbase + arow) * 128 + ks2 * 64 + acolb));
            const uint32_t ob = sw128((uint32_t)((mbase + arow) * 128 + ks2 * 64 + 32 + acolb));
            ldmatrix_x4(a0[0], a0[1], a0[2], a0[3], sbase + A_BUF(s) + oa);
            ldmatrix_x4(a1[0], a1[1], a1[2], a1[3], sbase + A_BUF(s) + ob);

            #pragma unroll
            for (int nt = 0; nt < 4; nt++) {
                const uint4 bf = (ks2 == 0) ? bf0[nt]
                    : __ldg(bfr + ((size_t)8 + (ncol * 4 + nt)) * 32 + lane);
                mma_f16(acc[nt][0], acc[nt][1], acc[nt][2], acc[nt][3],
                        a0[0], a0[1], a0[2], a0[3], bf.x, bf.y);
                mma_f16(acc[nt][0], acc[nt][1], acc[nt][2], acc[nt][3],
                        a1[0], a1[1], a1[2], a1[3], bf.z, bf.w);
            }
        }
    }

    __syncthreads();   // ldmatrix reads done before epilogue overwrites smem

    // ---- epilogue: transpose through smem, coalesced stores ----
    float* s_out = reinterpret_cast<float*>(smem);   // [OO][SOUT_STRIDE]
    {
        const int g   = lane >> 2;
        const int tig = lane & 3;
        #pragma unroll
        for (int nt = 0; nt < 4; nt++) {
            const int o  = ncol * 32 + nt * 8 + 2 * tig;
            const int p0 = mbase + g;
            s_out[o * SOUT_STRIDE + p0]            = acc[nt][0];
            s_out[(o + 1) * SOUT_STRIDE + p0]      = acc[nt][1];
            s_out[o * SOUT_STRIDE + p0 + 8]        = acc[nt][2];
            s_out[(o + 1) * SOUT_STRIDE + p0 + 8]  = acc[nt][3];
        }
    }
    __syncthreads();

    {
        float* ob = out + (size_t)b * OO * NPX + px0;
        #pragma unroll
        for (int i = 0; i < MPX * OO / THREADS; i++) {
            const int idx = i * THREADS + t;
            const int p = idx & (MPX - 1);
            const int o = idx >> 5;
            ob[(size_t)o * NPX + p] = s_out[o * SOUT_STRIDE + p] + __ldg(bias + o);
        }
    }
}

extern "C" void kernel_launch(void* const* d_in, const int* in_sizes, int n_in,
                              void* d_out, int out_size) {
    const float* x      = (const float*)d_in[0];
    const float* offset = (const float*)d_in[1];
    const float* mask   = (const float*)d_in[2];
    const float* weight = (const float*)d_in[3];
    const float* bias   = (const float*)d_in[4];
    float* out = (float*)d_out;

    prep_kernel<<<TRANS_BLOCKS + WPREP_BLOCKS, 256>>>(x, weight);

    cudaFuncSetAttribute(dcn_kernel,
                         cudaFuncAttributeMaxDynamicSharedMemorySize, SMEM_TOTAL);

    // PDL launch: dcn starts while prep runs; cudaGridDependencySynchronize()
    // inside dcn gates the first read of prep outputs.
    cudaLaunchConfig_t cfg = {};
    cfg.gridDim  = dim3(NPX / MPX, BB, 1);    // (288, 4) = 1152 blocks
    cfg.blockDim = dim3(THREADS, 1, 1);
    cfg.dynamicSmemBytes = SMEM_TOTAL;
    cudaLaunchAttribute attrs[1];
    attrs[0].id = cudaLaunchAttributeProgrammaticStreamSerialization;
    attrs[0].val.programmaticStreamSerializationAllowed = 1;
    cfg.attrs = attrs;
    cfg.numAttrs = 1;
    cudaLaunchKernelEx(&cfg, dcn_kernel, offset, mask, bias, out);
}